// round 1
// baseline (speedup 1.0000x reference)
#include <cuda_runtime.h>

// Problem constants
constexpr int H_   = 16;
constexpr int DM   = 1024;
constexpr int DK   = 64;
constexpr int BSZ  = 8;
constexpr int SEQL = 1024;
constexpr int MTOT = BSZ * SEQL;   // 8192

// Device scratch (allocation-free rule: static __device__ arrays)
__device__ float g_qh[(size_t)BSZ * H_ * SEQL * DK];     // [b,h,s,d]
__device__ float g_kh[(size_t)BSZ * H_ * SEQL * DK];
__device__ float g_vh[(size_t)BSZ * H_ * SEQL * DK];
__device__ float g_ctx[(size_t)BSZ * H_ * SEQL * DK];
__device__ float g_sc[(size_t)BSZ * H_ * SEQL * SEQL];   // scores/attn [bh,q,k] (536 MB)

// ---------------------------------------------------------------------------
// Projection: out_head[b,h,s,d] = (X @ W + bias) with head split.
// X: [8192,1024] row-major, W: [1024,1024] (k-major rows), bias: [1024].
// Tile 64x64, 256 threads, 4x4 micro-tile, K-step 16.
// which: 0->g_qh, 1->g_kh, 2->g_vh
// ---------------------------------------------------------------------------
__global__ __launch_bounds__(256) void mha_proj(const float* __restrict__ X,
                                                const float* __restrict__ W,
                                                const float* __restrict__ bias,
                                                int which) {
    __shared__ float Xs[16][64];   // [k][m] (K-major for vector LDS)
    __shared__ float Ws[16][64];   // [k][n]
    float* __restrict__ outHead = (which == 0) ? g_qh : (which == 1) ? g_kh : g_vh;

    const int tid = threadIdx.x;
    const int tx = tid & 15, ty = tid >> 4;
    const int n0 = blockIdx.x << 6;
    const int m0 = blockIdx.y << 6;
    const int lrow = tid & 63;            // X-load: row in tile
    const int lkc  = (tid >> 6) << 2;     // X-load: k offset (0,4,8,12)
    const int wk   = tid >> 4;            // W-load: k row
    const int wn   = (tid & 15) << 2;     // W-load: n offset

    float acc[4][4] = {};

    for (int k0 = 0; k0 < DM; k0 += 16) {
        float4 xv = *(const float4*)(X + (size_t)(m0 + lrow) * DM + k0 + lkc);
        Xs[lkc + 0][lrow] = xv.x;
        Xs[lkc + 1][lrow] = xv.y;
        Xs[lkc + 2][lrow] = xv.z;
        Xs[lkc + 3][lrow] = xv.w;
        *(float4*)&Ws[wk][wn] = *(const float4*)(W + (size_t)(k0 + wk) * DM + n0 + wn);
        __syncthreads();
        #pragma unroll
        for (int kk = 0; kk < 16; ++kk) {
            float a[4], b[4];
            *(float4*)a = *(const float4*)&Xs[kk][ty << 2];
            *(float4*)b = *(const float4*)&Ws[kk][tx << 2];
            #pragma unroll
            for (int i = 0; i < 4; ++i)
                #pragma unroll
                for (int j = 0; j < 4; ++j)
                    acc[i][j] = fmaf(a[i], b[j], acc[i][j]);
        }
        __syncthreads();
    }

    // n-tile is 64-wide and 64-aligned => single head per block
    const int h = blockIdx.x;             // n0/64
    float4 bb = *(const float4*)(bias + n0 + (tx << 2));
    #pragma unroll
    for (int i = 0; i < 4; ++i) {
        int m = m0 + (ty << 2) + i;
        int b = m >> 10, s = m & 1023;
        float4 o;
        o.x = acc[i][0] + bb.x;
        o.y = acc[i][1] + bb.y;
        o.z = acc[i][2] + bb.z;
        o.w = acc[i][3] + bb.w;
        *(float4*)(outHead + (size_t)((b * H_ + h) * SEQL + s) * DK + (tx << 2)) = o;
    }
}

// ---------------------------------------------------------------------------
// Scores: g_sc[z,q,k] = mask ? (qh[z,q,:]·kh[z,k,:]) * 0.125 : -1e9
// One block: 64 q x 64 k, full 64-d reduction. grid (16,16,128)
// ---------------------------------------------------------------------------
__global__ __launch_bounds__(256) void mha_scores(const int* __restrict__ mask) {
    __shared__ float Qs[64][64];   // [d][q]
    __shared__ float Ks[64][64];   // [d][k]
    const int tid = threadIdx.x;
    const int tx = tid & 15, ty = tid >> 4;
    const int z  = blockIdx.z;
    const int q0 = blockIdx.y << 6;
    const int k0 = blockIdx.x << 6;
    const int lrow = tid & 63;
    const int lc   = (tid >> 6) << 2;

    const float* qp = g_qh + ((size_t)z * SEQL + q0 + lrow) * DK;
    const float* kp = g_kh + ((size_t)z * SEQL + k0 + lrow) * DK;
    #pragma unroll
    for (int r = 0; r < 4; ++r) {
        int c = lc + (r << 4);
        float4 qv = *(const float4*)(qp + c);
        Qs[c + 0][lrow] = qv.x; Qs[c + 1][lrow] = qv.y;
        Qs[c + 2][lrow] = qv.z; Qs[c + 3][lrow] = qv.w;
        float4 kv = *(const float4*)(kp + c);
        Ks[c + 0][lrow] = kv.x; Ks[c + 1][lrow] = kv.y;
        Ks[c + 2][lrow] = kv.z; Ks[c + 3][lrow] = kv.w;
    }
    __syncthreads();

    float acc[4][4] = {};
    #pragma unroll 8
    for (int d = 0; d < 64; ++d) {
        float a[4], b[4];
        *(float4*)a = *(const float4*)&Qs[d][ty << 2];
        *(float4*)b = *(const float4*)&Ks[d][tx << 2];
        #pragma unroll
        for (int i = 0; i < 4; ++i)
            #pragma unroll
            for (int j = 0; j < 4; ++j)
                acc[i][j] = fmaf(a[i], b[j], acc[i][j]);
    }

    const int bidx = z >> 4;   // batch
    #pragma unroll
    for (int i = 0; i < 4; ++i) {
        int q = q0 + (ty << 2) + i;
        int4 mv = *(const int4*)(mask + ((size_t)bidx * SEQL + q) * SEQL + k0 + (tx << 2));
        float4 o;
        o.x = mv.x ? acc[i][0] * 0.125f : -1e9f;
        o.y = mv.y ? acc[i][1] * 0.125f : -1e9f;
        o.z = mv.z ? acc[i][2] * 0.125f : -1e9f;
        o.w = mv.w ? acc[i][3] * 0.125f : -1e9f;
        *(float4*)(g_sc + ((size_t)z * SEQL + q) * SEQL + k0 + (tx << 2)) = o;
    }
}

// ---------------------------------------------------------------------------
// Row softmax over 1024, in-place in g_sc. grid = 131072, block 256.
// ---------------------------------------------------------------------------
__global__ __launch_bounds__(256) void mha_softmax() {
    __shared__ float sred[8];
    const int t = threadIdx.x;
    float* p = g_sc + (size_t)blockIdx.x * SEQL;
    float4 v = *(float4*)(p + (t << 2));

    float mx = fmaxf(fmaxf(v.x, v.y), fmaxf(v.z, v.w));
    #pragma unroll
    for (int o = 16; o; o >>= 1) mx = fmaxf(mx, __shfl_xor_sync(0xffffffffu, mx, o));
    if ((t & 31) == 0) sred[t >> 5] = mx;
    __syncthreads();
    float bm = sred[0];
    #pragma unroll
    for (int i = 1; i < 8; ++i) bm = fmaxf(bm, sred[i]);
    __syncthreads();

    v.x = __expf(v.x - bm);
    v.y = __expf(v.y - bm);
    v.z = __expf(v.z - bm);
    v.w = __expf(v.w - bm);
    float s = v.x + v.y + v.z + v.w;
    #pragma unroll
    for (int o = 16; o; o >>= 1) s += __shfl_xor_sync(0xffffffffu, s, o);
    if ((t & 31) == 0) sred[t >> 5] = s;
    __syncthreads();
    float tot = 0.f;
    #pragma unroll
    for (int i = 0; i < 8; ++i) tot += sred[i];
    float inv = 1.0f / tot;

    v.x *= inv; v.y *= inv; v.z *= inv; v.w *= inv;
    *(float4*)(p + (t << 2)) = v;
}

// ---------------------------------------------------------------------------
// Context: g_ctx[z,q,d] = sum_k g_sc[z,q,k] * g_vh[z,k,d]. grid (16, 128)
// ---------------------------------------------------------------------------
__global__ __launch_bounds__(256) void mha_ctx() {
    __shared__ float Ps[16][64];   // [k][q]
    __shared__ float Vs[16][64];   // [k][d]
    const int tid = threadIdx.x;
    const int tx = tid & 15, ty = tid >> 4;
    const int z  = blockIdx.y;
    const int q0 = blockIdx.x << 6;
    const int lrow = tid & 63;
    const int lkc  = (tid >> 6) << 2;
    const int wk   = tid >> 4;
    const int wn   = (tid & 15) << 2;

    float acc[4][4] = {};
    for (int k0 = 0; k0 < SEQL; k0 += 16) {
        float4 pv = *(const float4*)(g_sc + ((size_t)z * SEQL + q0 + lrow) * SEQL + k0 + lkc);
        Ps[lkc + 0][lrow] = pv.x;
        Ps[lkc + 1][lrow] = pv.y;
        Ps[lkc + 2][lrow] = pv.z;
        Ps[lkc + 3][lrow] = pv.w;
        *(float4*)&Vs[wk][wn] =
            *(const float4*)(g_vh + ((size_t)z * SEQL + k0 + wk) * DK + wn);
        __syncthreads();
        #pragma unroll
        for (int kk = 0; kk < 16; ++kk) {
            float a[4], b[4];
            *(float4*)a = *(const float4*)&Ps[kk][ty << 2];
            *(float4*)b = *(const float4*)&Vs[kk][tx << 2];
            #pragma unroll
            for (int i = 0; i < 4; ++i)
                #pragma unroll
                for (int j = 0; j < 4; ++j)
                    acc[i][j] = fmaf(a[i], b[j], acc[i][j]);
        }
        __syncthreads();
    }
    #pragma unroll
    for (int i = 0; i < 4; ++i) {
        float4 o;
        o.x = acc[i][0]; o.y = acc[i][1]; o.z = acc[i][2]; o.w = acc[i][3];
        *(float4*)(g_ctx + ((size_t)z * SEQL + q0 + (ty << 2) + i) * DK + (tx << 2)) = o;
    }
}

// ---------------------------------------------------------------------------
// Output projection: Y = concat(ctx) @ Wo + bo. grid (16, 128)
// concat[m, h*64+d] = g_ctx[(b*H+h)*SEQ + s, d]
// ---------------------------------------------------------------------------
__global__ __launch_bounds__(256) void mha_out(const float* __restrict__ Wo,
                                               const float* __restrict__ bo,
                                               float* __restrict__ Y) {
    __shared__ float Xs[16][64];
    __shared__ float Ws[16][64];
    const int tid = threadIdx.x;
    const int tx = tid & 15, ty = tid >> 4;
    const int n0 = blockIdx.x << 6;
    const int m0 = blockIdx.y << 6;
    const int lrow = tid & 63;
    const int lkc  = (tid >> 6) << 2;
    const int wk   = tid >> 4;
    const int wn   = (tid & 15) << 2;

    const int ml = m0 + lrow;
    const int bl = ml >> 10, sl = ml & 1023;

    float acc[4][4] = {};
    for (int k0 = 0; k0 < DM; k0 += 16) {
        int kk0 = k0 + lkc;
        int h = kk0 >> 6, d = kk0 & 63;
        float4 xv = *(const float4*)(g_ctx + (size_t)((bl * H_ + h) * SEQL + sl) * DK + d);
        Xs[lkc + 0][lrow] = xv.x;
        Xs[lkc + 1][lrow] = xv.y;
        Xs[lkc + 2][lrow] = xv.z;
        Xs[lkc + 3][lrow] = xv.w;
        *(float4*)&Ws[wk][wn] = *(const float4*)(Wo + (size_t)(k0 + wk) * DM + n0 + wn);
        __syncthreads();
        #pragma unroll
        for (int kk = 0; kk < 16; ++kk) {
            float a[4], b[4];
            *(float4*)a = *(const float4*)&Xs[kk][ty << 2];
            *(float4*)b = *(const float4*)&Ws[kk][tx << 2];
            #pragma unroll
            for (int i = 0; i < 4; ++i)
                #pragma unroll
                for (int j = 0; j < 4; ++j)
                    acc[i][j] = fmaf(a[i], b[j], acc[i][j]);
        }
        __syncthreads();
    }

    float4 bb = *(const float4*)(bo + n0 + (tx << 2));
    #pragma unroll
    for (int i = 0; i < 4; ++i) {
        int m = m0 + (ty << 2) + i;
        float4 o;
        o.x = acc[i][0] + bb.x;
        o.y = acc[i][1] + bb.y;
        o.z = acc[i][2] + bb.z;
        o.w = acc[i][3] + bb.w;
        *(float4*)(Y + (size_t)m * DM + n0 + (tx << 2)) = o;
    }
}

// ---------------------------------------------------------------------------
extern "C" void kernel_launch(void* const* d_in, const int* in_sizes, int n_in,
                              void* d_out, int out_size) {
    (void)in_sizes; (void)n_in; (void)out_size;
    const float* q    = (const float*)d_in[0];
    const float* k    = (const float*)d_in[1];
    const float* v    = (const float*)d_in[2];
    const int*   mask = (const int*)d_in[3];
    const float* Wq = (const float*)d_in[4];
    const float* bq = (const float*)d_in[5];
    const float* Wk = (const float*)d_in[6];
    const float* bk = (const float*)d_in[7];
    const float* Wv = (const float*)d_in[8];
    const float* bv = (const float*)d_in[9];
    const float* Wo = (const float*)d_in[10];
    const float* bo = (const float*)d_in[11];
    float* out = (float*)d_out;

    dim3 blk(256);
    dim3 gProj(DM / 64, MTOT / 64);            // (16, 128)
    mha_proj<<<gProj, blk>>>(q, Wq, bq, 0);
    mha_proj<<<gProj, blk>>>(k, Wk, bk, 1);
    mha_proj<<<gProj, blk>>>(v, Wv, bv, 2);

    dim3 gSc(SEQL / 64, SEQL / 64, BSZ * H_);  // (16, 16, 128)
    mha_scores<<<gSc, blk>>>(mask);

    mha_softmax<<<BSZ * H_ * SEQL, blk>>>();   // 131072 rows

    dim3 gCtx(SEQL / 64, BSZ * H_);            // (16, 128)
    mha_ctx<<<gCtx, blk>>>();

    dim3 gOut(DM / 64, MTOT / 64);             // (16, 128)
    mha_out<<<gOut, blk>>>(Wo, bo, out);
}

// round 3
// speedup vs baseline: 1.6130x; 1.6130x over previous
#include <cuda_runtime.h>
#include <cuda_bf16.h>
#include <cstdint>

// Problem constants
constexpr int H_   = 16;
constexpr int DM   = 1024;
constexpr int DK   = 64;
constexpr int BSZ  = 8;
constexpr int SEQL = 1024;
constexpr int MTOT = BSZ * SEQL;   // 8192

// ---------------------------------------------------------------------------
// Device scratch
// ---------------------------------------------------------------------------
__device__ float g_qh[(size_t)BSZ * H_ * SEQL * DK];     // [b,h,s,d] fp32
__device__ float g_kh[(size_t)BSZ * H_ * SEQL * DK];
__device__ float g_vh[(size_t)BSZ * H_ * SEQL * DK];
__device__ float g_sc[(size_t)BSZ * H_ * SEQL * SEQL];   // scores/attn (536 MB)

// bf16 split activations (hi/lo): [8192,1024]
__device__ __align__(16) __nv_bfloat16 g_qah[(size_t)MTOT * DM], g_qal[(size_t)MTOT * DM];
__device__ __align__(16) __nv_bfloat16 g_kah[(size_t)MTOT * DM], g_kal[(size_t)MTOT * DM];
__device__ __align__(16) __nv_bfloat16 g_vah[(size_t)MTOT * DM], g_val_[(size_t)MTOT * DM];
// transposed weights [N,K] bf16 hi/lo
__device__ __align__(16) __nv_bfloat16 g_wqh[(size_t)DM * DM], g_wql[(size_t)DM * DM];
__device__ __align__(16) __nv_bfloat16 g_wkh[(size_t)DM * DM], g_wkl[(size_t)DM * DM];
__device__ __align__(16) __nv_bfloat16 g_wvh[(size_t)DM * DM], g_wvl[(size_t)DM * DM];
__device__ __align__(16) __nv_bfloat16 g_woh[(size_t)DM * DM], g_wol[(size_t)DM * DM];
// concat(ctx) bf16 hi/lo [8192,1024]
__device__ __align__(16) __nv_bfloat16 g_ch[(size_t)MTOT * DM], g_cl[(size_t)MTOT * DM];

// ---------------------------------------------------------------------------
// sm_80-class tensor-core helpers (compile on plain sm_103 target)
// ---------------------------------------------------------------------------
__device__ __forceinline__ uint32_t smem_u32(const void* p) {
    uint32_t a;
    asm("{ .reg .u64 t; cvta.to.shared.u64 t, %1; cvt.u32.u64 %0, t; }"
        : "=r"(a) : "l"(p));
    return a;
}
#define SWZ(o) ((o) ^ (((o) >> 3) & 0x70))

__device__ __forceinline__ void ldsm_x4(uint32_t r[4], uint32_t a) {
    asm volatile("ldmatrix.sync.aligned.m8n8.x4.shared.b16 {%0,%1,%2,%3}, [%4];"
                 : "=r"(r[0]), "=r"(r[1]), "=r"(r[2]), "=r"(r[3]) : "r"(a));
}
__device__ __forceinline__ void mma_bf16(float c[4], const uint32_t a[4], const uint32_t b[2]) {
    asm volatile(
        "mma.sync.aligned.m16n8k16.row.col.f32.bf16.bf16.f32 "
        "{%0,%1,%2,%3}, {%4,%5,%6,%7}, {%8,%9}, {%0,%1,%2,%3};"
        : "+f"(c[0]), "+f"(c[1]), "+f"(c[2]), "+f"(c[3])
        : "r"(a[0]), "r"(a[1]), "r"(a[2]), "r"(a[3]), "r"(b[0]), "r"(b[1]));
}
#define CP16(s, g) \
    asm volatile("cp.async.cg.shared.global [%0], [%1], 16;" :: "r"(s), "l"(g))
#define CP_COMMIT() asm volatile("cp.async.commit_group;" ::: "memory")
#define CP_WAIT1()  asm volatile("cp.async.wait_group 1;" ::: "memory")

// ---------------------------------------------------------------------------
// Prep: fp32 -> bf16 hi/lo split
// ---------------------------------------------------------------------------
__global__ __launch_bounds__(256) void cvt_split(const float* __restrict__ X, int sel) {
    __nv_bfloat16 *Hh, *Ll;
    if (sel == 0) { Hh = g_qah; Ll = g_qal; }
    else if (sel == 1) { Hh = g_kah; Ll = g_kal; }
    else { Hh = g_vah; Ll = g_val_; }
    size_t i = ((size_t)blockIdx.x * 256 + threadIdx.x) * 4;
    float4 v = *(const float4*)(X + i);
    __nv_bfloat16 h0 = __float2bfloat16(v.x), h1 = __float2bfloat16(v.y);
    __nv_bfloat16 h2 = __float2bfloat16(v.z), h3 = __float2bfloat16(v.w);
    __nv_bfloat16 l0 = __float2bfloat16(v.x - __bfloat162float(h0));
    __nv_bfloat16 l1 = __float2bfloat16(v.y - __bfloat162float(h1));
    __nv_bfloat16 l2 = __float2bfloat16(v.z - __bfloat162float(h2));
    __nv_bfloat16 l3 = __float2bfloat16(v.w - __bfloat162float(h3));
    *(__nv_bfloat162*)(Hh + i)     = __halves2bfloat162(h0, h1);
    *(__nv_bfloat162*)(Hh + i + 2) = __halves2bfloat162(h2, h3);
    *(__nv_bfloat162*)(Ll + i)     = __halves2bfloat162(l0, l1);
    *(__nv_bfloat162*)(Ll + i + 2) = __halves2bfloat162(l2, l3);
}

// Prep: W [K,N] fp32 -> Wt hi/lo bf16 [N,K]
__global__ __launch_bounds__(256) void cvt_wT(const float* __restrict__ W, int sel) {
    __nv_bfloat16 *Hh, *Ll;
    if (sel == 0) { Hh = g_wqh; Ll = g_wql; }
    else if (sel == 1) { Hh = g_wkh; Ll = g_wkl; }
    else if (sel == 2) { Hh = g_wvh; Ll = g_wvl; }
    else { Hh = g_woh; Ll = g_wol; }
    __shared__ float t[32][33];
    int x = blockIdx.x * 32 + threadIdx.x;   // n
    int y = blockIdx.y * 32 + threadIdx.y;   // k
    #pragma unroll
    for (int j = 0; j < 32; j += 8)
        t[threadIdx.y + j][threadIdx.x] = W[(size_t)(y + j) * DM + x];
    __syncthreads();
    int xo = blockIdx.y * 32 + threadIdx.x;  // k
    int yo = blockIdx.x * 32 + threadIdx.y;  // n
    #pragma unroll
    for (int j = 0; j < 32; j += 8) {
        float v = t[threadIdx.x][threadIdx.y + j];
        __nv_bfloat16 h = __float2bfloat16(v);
        __nv_bfloat16 l = __float2bfloat16(v - __bfloat162float(h));
        Hh[(size_t)(yo + j) * DM + xo] = h;
        Ll[(size_t)(yo + j) * DM + xo] = l;
    }
}

// ---------------------------------------------------------------------------
// HMMA split-bf16 GEMM: C[8192,1024] = A @ Bt^T + bias
// A hi/lo [M,K], Bt hi/lo [N,K]. CTA tile 128x128, KC=32, 2-stage cp.async.
// Smem row layout (128B, SW128 swizzle): [hi 64B | lo 64B] interleaved.
// sel 0/1/2 -> head-layout into g_qh/g_kh/g_vh; sel 3 -> flat to outF.
// ---------------------------------------------------------------------------
constexpr int SM_STAGE = 32768;          // A 16KB + B 16KB
constexpr int SM_BYTES = 2 * SM_STAGE;   // 64KB

extern __shared__ char dsm[];

__device__ __forceinline__ void issue_stage(
    uint32_t sbase, int stage,
    const __nv_bfloat16* __restrict__ Ah, const __nv_bfloat16* __restrict__ Al,
    const __nv_bfloat16* __restrict__ Bh, const __nv_bfloat16* __restrict__ Bl,
    int m0, int n0, int kc, int tid)
{
    uint32_t sa = sbase + stage * SM_STAGE;
    uint32_t sbB = sa + 16384;
    #pragma unroll
    for (int i = 0; i < 4; ++i) {
        int idx = tid + (i << 8);        // 0..1023
        int row = idx >> 3, c = idx & 7;
        uint32_t so = SWZ(row * 128 + c * 16);
        const __nv_bfloat16* srcA = (c < 4)
            ? (Ah + ((size_t)(m0 + row) << 10) + kc + (c << 3))
            : (Al + ((size_t)(m0 + row) << 10) + kc + ((c - 4) << 3));
        CP16(sa + so, srcA);
        const __nv_bfloat16* srcB = (c < 4)
            ? (Bh + ((size_t)(n0 + row) << 10) + kc + (c << 3))
            : (Bl + ((size_t)(n0 + row) << 10) + kc + ((c - 4) << 3));
        CP16(sbB + so, srcB);
    }
}

__global__ __launch_bounds__(256) void gemm_bf3(int sel, const float* __restrict__ bias,
                                                float* __restrict__ outF) {
    const __nv_bfloat16 *Ah, *Al, *Bh, *Bl;
    float* O;
    if (sel == 0) { Ah = g_qah; Al = g_qal; Bh = g_wqh; Bl = g_wql; O = g_qh; }
    else if (sel == 1) { Ah = g_kah; Al = g_kal; Bh = g_wkh; Bl = g_wkl; O = g_kh; }
    else if (sel == 2) { Ah = g_vah; Al = g_val_; Bh = g_wvh; Bl = g_wvl; O = g_vh; }
    else { Ah = g_ch; Al = g_cl; Bh = g_woh; Bl = g_wol; O = outF; }

    const uint32_t sbase = smem_u32(dsm);
    const int tid = threadIdx.x, lane = tid & 31, wid = tid >> 5;
    const int wm = wid >> 2, wn = wid & 3;          // 2 x 4 warp grid
    const int m0 = blockIdx.y << 7, n0 = blockIdx.x << 7;
    const int lrow = lane & 15, lchunk = lane >> 4;

    float acc[4][4][4] = {};

    issue_stage(sbase, 0, Ah, Al, Bh, Bl, m0, n0, 0, tid);  CP_COMMIT();
    issue_stage(sbase, 1, Ah, Al, Bh, Bl, m0, n0, 32, tid); CP_COMMIT();

    for (int it = 0; it < 32; ++it) {
        CP_WAIT1();
        __syncthreads();
        uint32_t sa = sbase + (it & 1) * SM_STAGE;
        uint32_t sb = sa + 16384;
        #pragma unroll
        for (int s = 0; s < 2; ++s) {
            const int coffH = s * 32 + lchunk * 16;
            const int coffL = 64 + coffH;
            uint32_t aH[4][4];
            #pragma unroll
            for (int f = 0; f < 4; ++f) {
                int r = (wm << 6) + (f << 4) + lrow;
                ldsm_x4(aH[f], sa + SWZ(r * 128 + coffH));
            }
            uint32_t bH[4][2];
            #pragma unroll
            for (int p = 0; p < 2; ++p) {
                int r = (wn << 5) + (p << 4) + lrow;
                uint32_t rr[4];
                ldsm_x4(rr, sb + SWZ(r * 128 + coffH));
                bH[p * 2][0] = rr[0]; bH[p * 2][1] = rr[2];
                bH[p * 2 + 1][0] = rr[1]; bH[p * 2 + 1][1] = rr[3];
            }
            #pragma unroll
            for (int f = 0; f < 4; ++f)
                #pragma unroll
                for (int n = 0; n < 4; ++n)
                    mma_bf16(acc[f][n], aH[f], bH[n]);
            // B-lo term (Ah x Bl)
            #pragma unroll
            for (int p = 0; p < 2; ++p) {
                int r = (wn << 5) + (p << 4) + lrow;
                uint32_t rr[4];
                ldsm_x4(rr, sb + SWZ(r * 128 + coffL));
                uint32_t bL0[2] = { rr[0], rr[2] };
                uint32_t bL1[2] = { rr[1], rr[3] };
                #pragma unroll
                for (int f = 0; f < 4; ++f) {
                    mma_bf16(acc[f][p * 2], aH[f], bL0);
                    mma_bf16(acc[f][p * 2 + 1], aH[f], bL1);
                }
            }
            // A-lo term (Al x Bh)
            #pragma unroll
            for (int f = 0; f < 4; ++f) {
                int r = (wm << 6) + (f << 4) + lrow;
                uint32_t aL[4];
                ldsm_x4(aL, sa + SWZ(r * 128 + coffL));
                #pragma unroll
                for (int n = 0; n < 4; ++n)
                    mma_bf16(acc[f][n], aL, bH[n]);
            }
        }
        __syncthreads();
        int nk = it + 2;
        if (nk < 32)
            issue_stage(sbase, nk & 1, Ah, Al, Bh, Bl, m0, n0, nk * 32, tid);
        CP_COMMIT();
    }

    // Epilogue
    const int lr = lane >> 2, lc = (lane & 3) << 1;
    #pragma unroll
    for (int f = 0; f < 4; ++f) {
        #pragma unroll
        for (int half = 0; half < 2; ++half) {
            int m = m0 + (wm << 6) + (f << 4) + lr + (half << 3);
            int b = m >> 10, s = m & 1023;
            #pragma unroll
            for (int n = 0; n < 4; ++n) {
                int ncol = n0 + (wn << 5) + (n << 3) + lc;
                float2 o;
                o.x = acc[f][n][half * 2 + 0] + __ldg(bias + ncol);
                o.y = acc[f][n][half * 2 + 1] + __ldg(bias + ncol + 1);
                if (sel == 3) {
                    *(float2*)(outF + (size_t)m * DM + ncol) = o;
                } else {
                    int h = ncol >> 6, d = ncol & 63;
                    *(float2*)(O + ((((size_t)b * H_ + h) << 10) + s) * DK + d) = o;
                }
            }
        }
    }
}

// ---------------------------------------------------------------------------
// Scores: g_sc[z,q,k] = mask ? (qh.kh)*0.125 : -1e9   (fp32 SIMT)
// ---------------------------------------------------------------------------
__global__ __launch_bounds__(256) void mha_scores(const int* __restrict__ mask) {
    __shared__ float Qs[64][64];
    __shared__ float Ks[64][64];
    const int tid = threadIdx.x;
    const int tx = tid & 15, ty = tid >> 4;
    const int z  = blockIdx.z;
    const int q0 = blockIdx.y << 6;
    const int k0 = blockIdx.x << 6;
    const int lrow = tid & 63;
    const int lc   = (tid >> 6) << 2;

    const float* qp = g_qh + ((size_t)z * SEQL + q0 + lrow) * DK;
    const float* kp = g_kh + ((size_t)z * SEQL + k0 + lrow) * DK;
    #pragma unroll
    for (int r = 0; r < 4; ++r) {
        int c = lc + (r << 4);
        float4 qv = *(const float4*)(qp + c);
        Qs[c + 0][lrow] = qv.x; Qs[c + 1][lrow] = qv.y;
        Qs[c + 2][lrow] = qv.z; Qs[c + 3][lrow] = qv.w;
        float4 kv = *(const float4*)(kp + c);
        Ks[c + 0][lrow] = kv.x; Ks[c + 1][lrow] = kv.y;
        Ks[c + 2][lrow] = kv.z; Ks[c + 3][lrow] = kv.w;
    }
    __syncthreads();

    float acc[4][4] = {};
    #pragma unroll 8
    for (int d = 0; d < 64; ++d) {
        float a[4], b[4];
        *(float4*)a = *(const float4*)&Qs[d][ty << 2];
        *(float4*)b = *(const float4*)&Ks[d][tx << 2];
        #pragma unroll
        for (int i = 0; i < 4; ++i)
            #pragma unroll
            for (int j = 0; j < 4; ++j)
                acc[i][j] = fmaf(a[i], b[j], acc[i][j]);
    }

    const int bidx = z >> 4;
    #pragma unroll
    for (int i = 0; i < 4; ++i) {
        int q = q0 + (ty << 2) + i;
        int4 mv = *(const int4*)(mask + ((size_t)bidx * SEQL + q) * SEQL + k0 + (tx << 2));
        float4 o;
        o.x = mv.x ? acc[i][0] * 0.125f : -1e9f;
        o.y = mv.y ? acc[i][1] * 0.125f : -1e9f;
        o.z = mv.z ? acc[i][2] * 0.125f : -1e9f;
        o.w = mv.w ? acc[i][3] * 0.125f : -1e9f;
        *(float4*)(g_sc + ((size_t)z * SEQL + q) * SEQL + k0 + (tx << 2)) = o;
    }
}

// ---------------------------------------------------------------------------
// Row softmax
// ---------------------------------------------------------------------------
__global__ __launch_bounds__(256) void mha_softmax() {
    __shared__ float sred[8];
    const int t = threadIdx.x;
    float* p = g_sc + (size_t)blockIdx.x * SEQL;
    float4 v = *(float4*)(p + (t << 2));

    float mx = fmaxf(fmaxf(v.x, v.y), fmaxf(v.z, v.w));
    #pragma unroll
    for (int o = 16; o; o >>= 1) mx = fmaxf(mx, __shfl_xor_sync(0xffffffffu, mx, o));
    if ((t & 31) == 0) sred[t >> 5] = mx;
    __syncthreads();
    float bm = sred[0];
    #pragma unroll
    for (int i = 1; i < 8; ++i) bm = fmaxf(bm, sred[i]);
    __syncthreads();

    v.x = __expf(v.x - bm);
    v.y = __expf(v.y - bm);
    v.z = __expf(v.z - bm);
    v.w = __expf(v.w - bm);
    float s = v.x + v.y + v.z + v.w;
    #pragma unroll
    for (int o = 16; o; o >>= 1) s += __shfl_xor_sync(0xffffffffu, s, o);
    if ((t & 31) == 0) sred[t >> 5] = s;
    __syncthreads();
    float tot = 0.f;
    #pragma unroll
    for (int i = 0; i < 8; ++i) tot += sred[i];
    float inv = 1.0f / tot;

    v.x *= inv; v.y *= inv; v.z *= inv; v.w *= inv;
    *(float4*)(p + (t << 2)) = v;
}

// ---------------------------------------------------------------------------
// Context: ctx = attn @ V; epilogue writes concat bf16 hi/lo
// ---------------------------------------------------------------------------
__global__ __launch_bounds__(256) void mha_ctx() {
    __shared__ float Ps[16][64];
    __shared__ float Vs[16][64];
    const int tid = threadIdx.x;
    const int tx = tid & 15, ty = tid >> 4;
    const int z  = blockIdx.y;
    const int q0 = blockIdx.x << 6;
    const int lrow = tid & 63;
    const int lkc  = (tid >> 6) << 2;
    const int wk   = tid >> 4;
    const int wn   = (tid & 15) << 2;

    float acc[4][4] = {};
    for (int k0 = 0; k0 < SEQL; k0 += 16) {
        float4 pv = *(const float4*)(g_sc + ((size_t)z * SEQL + q0 + lrow) * SEQL + k0 + lkc);
        Ps[lkc + 0][lrow] = pv.x;
        Ps[lkc + 1][lrow] = pv.y;
        Ps[lkc + 2][lrow] = pv.z;
        Ps[lkc + 3][lrow] = pv.w;
        *(float4*)&Vs[wk][wn] =
            *(const float4*)(g_vh + ((size_t)z * SEQL + k0 + wk) * DK + wn);
        __syncthreads();
        #pragma unroll
        for (int kk = 0; kk < 16; ++kk) {
            float a[4], b[4];
            *(float4*)a = *(const float4*)&Ps[kk][ty << 2];
            *(float4*)b = *(const float4*)&Vs[kk][tx << 2];
            #pragma unroll
            for (int i = 0; i < 4; ++i)
                #pragma unroll
                for (int j = 0; j < 4; ++j)
                    acc[i][j] = fmaf(a[i], b[j], acc[i][j]);
        }
        __syncthreads();
    }
    // write concat hi/lo bf16: row = b*1024+q, col = h*64+d
    const int b = z >> 4, h = z & 15;
    #pragma unroll
    for (int i = 0; i < 4; ++i) {
        int q = q0 + (ty << 2) + i;
        size_t base = (((size_t)b << 10) + q) * DM + (h << 6) + (tx << 2);
        __nv_bfloat16 hh[4], ll[4];
        #pragma unroll
        for (int j = 0; j < 4; ++j) {
            float x = acc[i][j];
            hh[j] = __float2bfloat16(x);
            ll[j] = __float2bfloat16(x - __bfloat162float(hh[j]));
        }
        *(__nv_bfloat162*)(g_ch + base)     = __halves2bfloat162(hh[0], hh[1]);
        *(__nv_bfloat162*)(g_ch + base + 2) = __halves2bfloat162(hh[2], hh[3]);
        *(__nv_bfloat162*)(g_cl + base)     = __halves2bfloat162(ll[0], ll[1]);
        *(__nv_bfloat162*)(g_cl + base + 2) = __halves2bfloat162(ll[2], ll[3]);
    }
}

// ---------------------------------------------------------------------------
extern "C" void kernel_launch(void* const* d_in, const int* in_sizes, int n_in,
                              void* d_out, int out_size) {
    (void)in_sizes; (void)n_in; (void)out_size;
    const float* q    = (const float*)d_in[0];
    const float* k    = (const float*)d_in[1];
    const float* v    = (const float*)d_in[2];
    const int*   mask = (const int*)d_in[3];
    const float* Wq = (const float*)d_in[4];
    const float* bq = (const float*)d_in[5];
    const float* Wk = (const float*)d_in[6];
    const float* bk = (const float*)d_in[7];
    const float* Wv = (const float*)d_in[8];
    const float* bv = (const float*)d_in[9];
    const float* Wo = (const float*)d_in[10];
    const float* bo = (const float*)d_in[11];
    float* out = (float*)d_out;

    cudaFuncSetAttribute(gemm_bf3, cudaFuncAttributeMaxDynamicSharedMemorySize, SM_BYTES);

    // Prep: split activations, transpose+split weights
    cvt_split<<<(MTOT * DM) / (256 * 4), 256>>>(q, 0);
    cvt_split<<<(MTOT * DM) / (256 * 4), 256>>>(k, 1);
    cvt_split<<<(MTOT * DM) / (256 * 4), 256>>>(v, 2);
    dim3 tB(32, 8), tG(DM / 32, DM / 32);
    cvt_wT<<<tG, tB>>>(Wq, 0);
    cvt_wT<<<tG, tB>>>(Wk, 1);
    cvt_wT<<<tG, tB>>>(Wv, 2);
    cvt_wT<<<tG, tB>>>(Wo, 3);

    // Projections (HMMA split-bf16)
    dim3 gg(DM / 128, MTOT / 128);   // (8, 64)
    gemm_bf3<<<gg, 256, SM_BYTES>>>(0, bq, nullptr);
    gemm_bf3<<<gg, 256, SM_BYTES>>>(1, bk, nullptr);
    gemm_bf3<<<gg, 256, SM_BYTES>>>(2, bv, nullptr);

    // Attention (SIMT this round)
    dim3 blk(256);
    dim3 gSc(SEQL / 64, SEQL / 64, BSZ * H_);
    mha_scores<<<gSc, blk>>>(mask);
    mha_softmax<<<BSZ * H_ * SEQL, blk>>>();
    dim3 gCtx(SEQL / 64, BSZ * H_);
    mha_ctx<<<gCtx, blk>>>();

    // Output projection (HMMA split-bf16)
    gemm_bf3<<<gg, 256, SM_BYTES>>>(3, bo, out);
}

// round 4
// speedup vs baseline: 3.0913x; 1.9165x over previous
#include <cuda_runtime.h>
#include <cuda_bf16.h>
#include <cstdint>

// Problem constants
constexpr int H_   = 16;
constexpr int DM   = 1024;
constexpr int DK   = 64;
constexpr int BSZ  = 8;
constexpr int SEQL = 1024;
constexpr int MTOT = BSZ * SEQL;   // 8192

// ---------------------------------------------------------------------------
// Device scratch
// ---------------------------------------------------------------------------
// bf16 split activations (hi/lo): [8192,1024]
__device__ __align__(16) __nv_bfloat16 g_qah[(size_t)MTOT * DM], g_qal[(size_t)MTOT * DM];
__device__ __align__(16) __nv_bfloat16 g_kah[(size_t)MTOT * DM], g_kal[(size_t)MTOT * DM];
__device__ __align__(16) __nv_bfloat16 g_vah[(size_t)MTOT * DM], g_val_[(size_t)MTOT * DM];
// transposed weights [N,K] bf16 hi/lo
__device__ __align__(16) __nv_bfloat16 g_wqh[(size_t)DM * DM], g_wql[(size_t)DM * DM];
__device__ __align__(16) __nv_bfloat16 g_wkh[(size_t)DM * DM], g_wkl[(size_t)DM * DM];
__device__ __align__(16) __nv_bfloat16 g_wvh[(size_t)DM * DM], g_wvl[(size_t)DM * DM];
__device__ __align__(16) __nv_bfloat16 g_woh[(size_t)DM * DM], g_wol[(size_t)DM * DM];
// head-layout projected Q/K/V split bf16: [b*H+h][s][d]
__device__ __align__(16) __nv_bfloat16 g_qhh[(size_t)BSZ * H_ * SEQL * DK], g_qhl[(size_t)BSZ * H_ * SEQL * DK];
__device__ __align__(16) __nv_bfloat16 g_khh[(size_t)BSZ * H_ * SEQL * DK], g_khl[(size_t)BSZ * H_ * SEQL * DK];
__device__ __align__(16) __nv_bfloat16 g_vhh[(size_t)BSZ * H_ * SEQL * DK], g_vhl[(size_t)BSZ * H_ * SEQL * DK];
// concat(ctx) bf16 hi/lo [8192,1024]
__device__ __align__(16) __nv_bfloat16 g_ch[(size_t)MTOT * DM], g_cl[(size_t)MTOT * DM];
// byte-packed mask [b][q][k]
__device__ __align__(16) unsigned char g_m8[(size_t)BSZ * SEQL * SEQL];

// ---------------------------------------------------------------------------
// helpers
// ---------------------------------------------------------------------------
__device__ __forceinline__ uint32_t smem_u32(const void* p) {
    uint32_t a;
    asm("{ .reg .u64 t; cvta.to.shared.u64 t, %1; cvt.u32.u64 %0, t; }"
        : "=r"(a) : "l"(p));
    return a;
}
#define SWZ(o) ((o) ^ (((o) >> 3) & 0x70))

__device__ __forceinline__ void ldsm_x4(uint32_t r[4], uint32_t a) {
    asm volatile("ldmatrix.sync.aligned.m8n8.x4.shared.b16 {%0,%1,%2,%3}, [%4];"
                 : "=r"(r[0]), "=r"(r[1]), "=r"(r[2]), "=r"(r[3]) : "r"(a));
}
__device__ __forceinline__ void ldsm_x4_t(uint32_t r[4], uint32_t a) {
    asm volatile("ldmatrix.sync.aligned.m8n8.x4.trans.shared.b16 {%0,%1,%2,%3}, [%4];"
                 : "=r"(r[0]), "=r"(r[1]), "=r"(r[2]), "=r"(r[3]) : "r"(a));
}
__device__ __forceinline__ void mma_bf16(float c[4], const uint32_t a[4], const uint32_t b[2]) {
    asm volatile(
        "mma.sync.aligned.m16n8k16.row.col.f32.bf16.bf16.f32 "
        "{%0,%1,%2,%3}, {%4,%5,%6,%7}, {%8,%9}, {%0,%1,%2,%3};"
        : "+f"(c[0]), "+f"(c[1]), "+f"(c[2]), "+f"(c[3])
        : "r"(a[0]), "r"(a[1]), "r"(a[2]), "r"(a[3]), "r"(b[0]), "r"(b[1]));
}
#define CP16(s, g) \
    asm volatile("cp.async.cg.shared.global [%0], [%1], 16;" :: "r"(s), "l"(g))
#define CP_COMMIT() asm volatile("cp.async.commit_group;" ::: "memory")
#define CP_WAIT1()  asm volatile("cp.async.wait_group 1;" ::: "memory")

__device__ __forceinline__ void split2(float x, float y, uint32_t& hi, uint32_t& lo) {
    __nv_bfloat16 hx = __float2bfloat16(x), hy = __float2bfloat16(y);
    __nv_bfloat16 lx = __float2bfloat16(x - __bfloat162float(hx));
    __nv_bfloat16 ly = __float2bfloat16(y - __bfloat162float(hy));
    __nv_bfloat162 Hh = __halves2bfloat162(hx, hy), Ll = __halves2bfloat162(lx, ly);
    hi = *(uint32_t*)&Hh; lo = *(uint32_t*)&Ll;
}

// ---------------------------------------------------------------------------
// Prep kernels
// ---------------------------------------------------------------------------
__global__ __launch_bounds__(256) void cvt_split(const float* __restrict__ X, int sel) {
    __nv_bfloat16 *Hh, *Ll;
    if (sel == 0) { Hh = g_qah; Ll = g_qal; }
    else if (sel == 1) { Hh = g_kah; Ll = g_kal; }
    else { Hh = g_vah; Ll = g_val_; }
    size_t i = ((size_t)blockIdx.x * 256 + threadIdx.x) * 4;
    float4 v = *(const float4*)(X + i);
    __nv_bfloat16 h0 = __float2bfloat16(v.x), h1 = __float2bfloat16(v.y);
    __nv_bfloat16 h2 = __float2bfloat16(v.z), h3 = __float2bfloat16(v.w);
    __nv_bfloat16 l0 = __float2bfloat16(v.x - __bfloat162float(h0));
    __nv_bfloat16 l1 = __float2bfloat16(v.y - __bfloat162float(h1));
    __nv_bfloat16 l2 = __float2bfloat16(v.z - __bfloat162float(h2));
    __nv_bfloat16 l3 = __float2bfloat16(v.w - __bfloat162float(h3));
    *(__nv_bfloat162*)(Hh + i)     = __halves2bfloat162(h0, h1);
    *(__nv_bfloat162*)(Hh + i + 2) = __halves2bfloat162(h2, h3);
    *(__nv_bfloat162*)(Ll + i)     = __halves2bfloat162(l0, l1);
    *(__nv_bfloat162*)(Ll + i + 2) = __halves2bfloat162(l2, l3);
}

__global__ __launch_bounds__(256) void cvt_wT(const float* __restrict__ W, int sel) {
    __nv_bfloat16 *Hh, *Ll;
    if (sel == 0) { Hh = g_wqh; Ll = g_wql; }
    else if (sel == 1) { Hh = g_wkh; Ll = g_wkl; }
    else if (sel == 2) { Hh = g_wvh; Ll = g_wvl; }
    else { Hh = g_woh; Ll = g_wol; }
    __shared__ float t[32][33];
    int x = blockIdx.x * 32 + threadIdx.x;   // n
    int y = blockIdx.y * 32 + threadIdx.y;   // k
    #pragma unroll
    for (int j = 0; j < 32; j += 8)
        t[threadIdx.y + j][threadIdx.x] = W[(size_t)(y + j) * DM + x];
    __syncthreads();
    int xo = blockIdx.y * 32 + threadIdx.x;  // k
    int yo = blockIdx.x * 32 + threadIdx.y;  // n
    #pragma unroll
    for (int j = 0; j < 32; j += 8) {
        float v = t[threadIdx.x][threadIdx.y + j];
        __nv_bfloat16 h = __float2bfloat16(v);
        __nv_bfloat16 l = __float2bfloat16(v - __bfloat162float(h));
        Hh[(size_t)(yo + j) * DM + xo] = h;
        Ll[(size_t)(yo + j) * DM + xo] = l;
    }
}

__global__ __launch_bounds__(256) void pack_mask(const int* __restrict__ m) {
    size_t i = ((size_t)blockIdx.x * 256 + threadIdx.x) * 4;
    int4 v = *(const int4*)(m + i);
    uchar4 o;
    o.x = (unsigned char)v.x; o.y = (unsigned char)v.y;
    o.z = (unsigned char)v.z; o.w = (unsigned char)v.w;
    *(uchar4*)(g_m8 + i) = o;
}

// ---------------------------------------------------------------------------
// HMMA split-bf16 GEMM (as R3). sel 0/1/2 -> split-bf16 head layout (Q scaled
// by 0.125); sel 3 -> fp32 flat output.
// ---------------------------------------------------------------------------
constexpr int SM_STAGE = 32768;
constexpr int SM_BYTES = 2 * SM_STAGE;

extern __shared__ char dsm[];

__device__ __forceinline__ void issue_stage(
    uint32_t sbase, int stage,
    const __nv_bfloat16* __restrict__ Ah, const __nv_bfloat16* __restrict__ Al,
    const __nv_bfloat16* __restrict__ Bh, const __nv_bfloat16* __restrict__ Bl,
    int m0, int n0, int kc, int tid)
{
    uint32_t sa = sbase + stage * SM_STAGE;
    uint32_t sbB = sa + 16384;
    #pragma unroll
    for (int i = 0; i < 4; ++i) {
        int idx = tid + (i << 8);
        int row = idx >> 3, c = idx & 7;
        uint32_t so = SWZ(row * 128 + c * 16);
        const __nv_bfloat16* srcA = (c < 4)
            ? (Ah + ((size_t)(m0 + row) << 10) + kc + (c << 3))
            : (Al + ((size_t)(m0 + row) << 10) + kc + ((c - 4) << 3));
        CP16(sa + so, srcA);
        const __nv_bfloat16* srcB = (c < 4)
            ? (Bh + ((size_t)(n0 + row) << 10) + kc + (c << 3))
            : (Bl + ((size_t)(n0 + row) << 10) + kc + ((c - 4) << 3));
        CP16(sbB + so, srcB);
    }
}

__global__ __launch_bounds__(256) void gemm_bf3(int sel, const float* __restrict__ bias,
                                                float* __restrict__ outF) {
    const __nv_bfloat16 *Ah, *Al, *Bh, *Bl;
    __nv_bfloat16 *OH = nullptr, *OL = nullptr;
    if (sel == 0) { Ah = g_qah; Al = g_qal; Bh = g_wqh; Bl = g_wql; OH = g_qhh; OL = g_qhl; }
    else if (sel == 1) { Ah = g_kah; Al = g_kal; Bh = g_wkh; Bl = g_wkl; OH = g_khh; OL = g_khl; }
    else if (sel == 2) { Ah = g_vah; Al = g_val_; Bh = g_wvh; Bl = g_wvl; OH = g_vhh; OL = g_vhl; }
    else { Ah = g_ch; Al = g_cl; Bh = g_woh; Bl = g_wol; }

    const uint32_t sbase = smem_u32(dsm);
    const int tid = threadIdx.x, lane = tid & 31, wid = tid >> 5;
    const int wm = wid >> 2, wn = wid & 3;
    const int m0 = blockIdx.y << 7, n0 = blockIdx.x << 7;
    const int lrow = lane & 15, lchunk = lane >> 4;

    float acc[4][4][4] = {};

    issue_stage(sbase, 0, Ah, Al, Bh, Bl, m0, n0, 0, tid);  CP_COMMIT();
    issue_stage(sbase, 1, Ah, Al, Bh, Bl, m0, n0, 32, tid); CP_COMMIT();

    for (int it = 0; it < 32; ++it) {
        CP_WAIT1();
        __syncthreads();
        uint32_t sa = sbase + (it & 1) * SM_STAGE;
        uint32_t sb = sa + 16384;
        #pragma unroll
        for (int s = 0; s < 2; ++s) {
            const int coffH = s * 32 + lchunk * 16;
            const int coffL = 64 + coffH;
            uint32_t aH[4][4];
            #pragma unroll
            for (int f = 0; f < 4; ++f) {
                int r = (wm << 6) + (f << 4) + lrow;
                ldsm_x4(aH[f], sa + SWZ(r * 128 + coffH));
            }
            uint32_t bH[4][2];
            #pragma unroll
            for (int p = 0; p < 2; ++p) {
                int r = (wn << 5) + (p << 4) + lrow;
                uint32_t rr[4];
                ldsm_x4(rr, sb + SWZ(r * 128 + coffH));
                bH[p * 2][0] = rr[0]; bH[p * 2][1] = rr[2];
                bH[p * 2 + 1][0] = rr[1]; bH[p * 2 + 1][1] = rr[3];
            }
            #pragma unroll
            for (int f = 0; f < 4; ++f)
                #pragma unroll
                for (int n = 0; n < 4; ++n)
                    mma_bf16(acc[f][n], aH[f], bH[n]);
            #pragma unroll
            for (int p = 0; p < 2; ++p) {
                int r = (wn << 5) + (p << 4) + lrow;
                uint32_t rr[4];
                ldsm_x4(rr, sb + SWZ(r * 128 + coffL));
                uint32_t bL0[2] = { rr[0], rr[2] };
                uint32_t bL1[2] = { rr[1], rr[3] };
                #pragma unroll
                for (int f = 0; f < 4; ++f) {
                    mma_bf16(acc[f][p * 2], aH[f], bL0);
                    mma_bf16(acc[f][p * 2 + 1], aH[f], bL1);
                }
            }
            #pragma unroll
            for (int f = 0; f < 4; ++f) {
                int r = (wm << 6) + (f << 4) + lrow;
                uint32_t aL[4];
                ldsm_x4(aL, sa + SWZ(r * 128 + coffL));
                #pragma unroll
                for (int n = 0; n < 4; ++n)
                    mma_bf16(acc[f][n], aL, bH[n]);
            }
        }
        __syncthreads();
        int nk = it + 2;
        if (nk < 32)
            issue_stage(sbase, nk & 1, Ah, Al, Bh, Bl, m0, n0, nk * 32, tid);
        CP_COMMIT();
    }

    const int lr = lane >> 2, lc = (lane & 3) << 1;
    const float scale = (sel == 0) ? 0.125f : 1.0f;
    #pragma unroll
    for (int f = 0; f < 4; ++f) {
        #pragma unroll
        for (int half = 0; half < 2; ++half) {
            int m = m0 + (wm << 6) + (f << 4) + lr + (half << 3);
            int b = m >> 10, s = m & 1023;
            #pragma unroll
            for (int n = 0; n < 4; ++n) {
                int ncol = n0 + (wn << 5) + (n << 3) + lc;
                float x0 = acc[f][n][half * 2 + 0] + __ldg(bias + ncol);
                float x1 = acc[f][n][half * 2 + 1] + __ldg(bias + ncol + 1);
                if (sel == 3) {
                    float2 o; o.x = x0; o.y = x1;
                    *(float2*)(outF + (size_t)m * DM + ncol) = o;
                } else {
                    x0 *= scale; x1 *= scale;
                    int hh = ncol >> 6, d = ncol & 63;
                    size_t off = ((((size_t)b * H_ + hh) << 10) + s) * DK + d;
                    uint32_t hi, lo;
                    split2(x0, x1, hi, lo);
                    *(uint32_t*)(OH + off) = hi;
                    *(uint32_t*)(OL + off) = lo;
                }
            }
        }
    }
}

// ---------------------------------------------------------------------------
// Fused flash attention (split-bf16 HMMA).
// Grid (8 q-tiles, 128 bh). 256 threads = 8 warps, warp w owns q rows [16w,16w+16).
// ---------------------------------------------------------------------------
constexpr int F_QH = 0, F_QL = 16384;
constexpr int F_STG = 32768;
constexpr int F_KH = 0, F_KL = 16384, F_VH = 32768, F_VL = 49152, F_MSK = 65536;
constexpr int F_MROW = 144;                       // padded mask row stride
constexpr int F_STGSZ = 65536 + 128 * F_MROW;     // 83968
constexpr int F_SMEM = F_STG + 2 * F_STGSZ;       // 200704

__device__ __forceinline__ void issue_kv(uint32_t sbase, int stage, int z, int b,
                                         int q0, int k0, int tid) {
    uint32_t s = sbase + F_STG + stage * F_STGSZ;
    #pragma unroll
    for (int i = 0; i < 4; ++i) {
        int idx = tid + (i << 8);
        int r = idx >> 3, c = idx & 7;
        uint32_t so = SWZ(r * 128 + c * 16);
        size_t go = ((size_t)z * SEQL + k0 + r) * DK + (c << 3);
        CP16(s + F_KH + so, g_khh + go);
        CP16(s + F_KL + so, g_khl + go);
        CP16(s + F_VH + so, g_vhh + go);
        CP16(s + F_VL + so, g_vhl + go);
    }
    #pragma unroll
    for (int i = 0; i < 4; ++i) {
        int idx = tid + (i << 8);
        int r = idx >> 3, c = idx & 7;
        CP16(s + F_MSK + r * F_MROW + c * 16,
             g_m8 + ((size_t)b * SEQL + q0 + r) * SEQL + k0 + (c << 4));
    }
}

__global__ void __launch_bounds__(256, 1) flash_attn() {
    const uint32_t sbase = smem_u32(dsm);
    const int tid = threadIdx.x, lane = tid & 31, w = tid >> 5;
    const int z = blockIdx.y;
    const int b = z >> 4, h = z & 15;
    const int q0 = blockIdx.x << 7;

    // Q tile loads (group 0)
    #pragma unroll
    for (int i = 0; i < 4; ++i) {
        int idx = tid + (i << 8);
        int r = idx >> 3, c = idx & 7;
        uint32_t so = SWZ(r * 128 + c * 16);
        size_t go = ((size_t)z * SEQL + q0 + r) * DK + (c << 3);
        CP16(sbase + F_QH + so, g_qhh + go);
        CP16(sbase + F_QL + so, g_qhl + go);
    }
    CP_COMMIT();
    issue_kv(sbase, 0, z, b, q0, 0, tid);   CP_COMMIT();
    issue_kv(sbase, 1, z, b, q0, 128, tid); CP_COMMIT();

    CP_WAIT1();           // Q + stage0 done
    __syncthreads();

    // Q fragments (held in regs for whole loop)
    uint32_t qh[4][4], ql[4][4];
    #pragma unroll
    for (int c = 0; c < 4; ++c) {
        int r = (w << 4) + (lane & 15);
        uint32_t coff = (c << 5) + ((lane >> 4) << 4);
        ldsm_x4(qh[c], sbase + F_QH + SWZ(r * 128 + coff));
        ldsm_x4(ql[c], sbase + F_QL + SWZ(r * 128 + coff));
    }

    float oacc[8][4] = {};
    float ml0 = -1e30f, ml1 = -1e30f, ll0 = 0.f, ll1 = 0.f;
    const int rql = (w << 4) + (lane >> 2);      // local q row (first of pair)
    const int cb2 = (lane & 3) << 1;

    for (int kt = 0; kt < 8; ++kt) {
        if (kt) { CP_WAIT1(); __syncthreads(); }
        uint32_t s = sbase + F_STG + (kt & 1) * F_STGSZ;

        float sacc[16][4] = {};
        // ---- S = Q K^T (3-term split) ----
        #pragma unroll
        for (int c = 0; c < 4; ++c) {
            #pragma unroll
            for (int p = 0; p < 8; ++p) {
                int r = (p << 4) + (lane & 15);
                uint32_t coff = (c << 5) + ((lane >> 4) << 4);
                uint32_t rh[4], rl[4];
                ldsm_x4(rh, s + F_KH + SWZ(r * 128 + coff));
                ldsm_x4(rl, s + F_KL + SWZ(r * 128 + coff));
                uint32_t bh0[2] = { rh[0], rh[2] }, bh1[2] = { rh[1], rh[3] };
                uint32_t bl0[2] = { rl[0], rl[2] }, bl1[2] = { rl[1], rl[3] };
                mma_bf16(sacc[2 * p],     qh[c], bh0);
                mma_bf16(sacc[2 * p],     qh[c], bl0);
                mma_bf16(sacc[2 * p],     ql[c], bh0);
                mma_bf16(sacc[2 * p + 1], qh[c], bh1);
                mma_bf16(sacc[2 * p + 1], qh[c], bl1);
                mma_bf16(sacc[2 * p + 1], ql[c], bh1);
            }
        }

        // ---- mask + online softmax ----
        uint32_t mb = s + F_MSK + rql * F_MROW + cb2;
        float tm0 = -1e30f, tm1 = -1e30f;
        #pragma unroll
        for (int n = 0; n < 16; ++n) {
            unsigned short m01, m23;
            asm volatile("ld.shared.u16 %0, [%1];" : "=h"(m01) : "r"(mb + (n << 3)));
            asm volatile("ld.shared.u16 %0, [%1];" : "=h"(m23) : "r"(mb + (n << 3) + 8 * F_MROW));
            float v0 = (m01 & 0x00FF) ? sacc[n][0] : -1e9f;
            float v1 = (m01 & 0xFF00) ? sacc[n][1] : -1e9f;
            float v2 = (m23 & 0x00FF) ? sacc[n][2] : -1e9f;
            float v3 = (m23 & 0xFF00) ? sacc[n][3] : -1e9f;
            sacc[n][0] = v0; sacc[n][1] = v1; sacc[n][2] = v2; sacc[n][3] = v3;
            tm0 = fmaxf(tm0, fmaxf(v0, v1));
            tm1 = fmaxf(tm1, fmaxf(v2, v3));
        }
        tm0 = fmaxf(tm0, __shfl_xor_sync(0xffffffffu, tm0, 1));
        tm0 = fmaxf(tm0, __shfl_xor_sync(0xffffffffu, tm0, 2));
        tm1 = fmaxf(tm1, __shfl_xor_sync(0xffffffffu, tm1, 1));
        tm1 = fmaxf(tm1, __shfl_xor_sync(0xffffffffu, tm1, 2));
        float mn0 = fmaxf(ml0, tm0), mn1 = fmaxf(ml1, tm1);
        float al0 = __expf(ml0 - mn0), al1 = __expf(ml1 - mn1);
        ml0 = mn0; ml1 = mn1;
        float ts0 = 0.f, ts1 = 0.f;
        #pragma unroll
        for (int n = 0; n < 16; ++n) {
            float p0 = __expf(sacc[n][0] - mn0);
            float p1 = __expf(sacc[n][1] - mn0);
            float p2 = __expf(sacc[n][2] - mn1);
            float p3 = __expf(sacc[n][3] - mn1);
            sacc[n][0] = p0; sacc[n][1] = p1; sacc[n][2] = p2; sacc[n][3] = p3;
            ts0 += p0 + p1; ts1 += p2 + p3;
        }
        ts0 += __shfl_xor_sync(0xffffffffu, ts0, 1);
        ts0 += __shfl_xor_sync(0xffffffffu, ts0, 2);
        ts1 += __shfl_xor_sync(0xffffffffu, ts1, 1);
        ts1 += __shfl_xor_sync(0xffffffffu, ts1, 2);
        ll0 = ll0 * al0 + ts0;
        ll1 = ll1 * al1 + ts1;
        #pragma unroll
        for (int nd = 0; nd < 8; ++nd) {
            oacc[nd][0] *= al0; oacc[nd][1] *= al0;
            oacc[nd][2] *= al1; oacc[nd][3] *= al1;
        }

        // ---- O += P V (3-term split; V via ldmatrix.trans) ----
        #pragma unroll
        for (int j = 0; j < 8; ++j) {
            uint32_t aph[4], apl[4];
            split2(sacc[2 * j][0],     sacc[2 * j][1],     aph[0], apl[0]);
            split2(sacc[2 * j][2],     sacc[2 * j][3],     aph[1], apl[1]);
            split2(sacc[2 * j + 1][0], sacc[2 * j + 1][1], aph[2], apl[2]);
            split2(sacc[2 * j + 1][2], sacc[2 * j + 1][3], aph[3], apl[3]);
            #pragma unroll
            for (int nd = 0; nd < 4; ++nd) {
                int r = (j << 4) + (lane & 15);
                uint32_t coff = (nd << 5) + ((lane >> 4) << 4);
                uint32_t vh[4], vl[4];
                ldsm_x4_t(vh, s + F_VH + SWZ(r * 128 + coff));
                ldsm_x4_t(vl, s + F_VL + SWZ(r * 128 + coff));
                uint32_t bh0[2] = { vh[0], vh[1] }, bh1[2] = { vh[2], vh[3] };
                uint32_t bl0[2] = { vl[0], vl[1] }, bl1[2] = { vl[2], vl[3] };
                mma_bf16(oacc[2 * nd],     aph, bh0);
                mma_bf16(oacc[2 * nd],     aph, bl0);
                mma_bf16(oacc[2 * nd],     apl, bh0);
                mma_bf16(oacc[2 * nd + 1], aph, bh1);
                mma_bf16(oacc[2 * nd + 1], aph, bl1);
                mma_bf16(oacc[2 * nd + 1], apl, bh1);
            }
        }

        __syncthreads();              // all warps done with this stage buffer
        int nk = kt + 2;
        if (nk < 8) issue_kv(sbase, nk & 1, z, b, q0, nk << 7, tid);
        CP_COMMIT();
    }

    // ---- epilogue: O/l -> split-bf16 concat ----
    float inv0 = 1.0f / ll0, inv1 = 1.0f / ll1;
    int qr = q0 + rql;
    size_t base0 = (((size_t)b << 10) + qr) * DM + (h << 6);
    size_t base1 = base0 + (size_t)8 * DM;
    #pragma unroll
    for (int nd = 0; nd < 8; ++nd) {
        int d = (nd << 3) + cb2;
        uint32_t hi, lo;
        split2(oacc[nd][0] * inv0, oacc[nd][1] * inv0, hi, lo);
        *(uint32_t*)(g_ch + base0 + d) = hi;
        *(uint32_t*)(g_cl + base0 + d) = lo;
        split2(oacc[nd][2] * inv1, oacc[nd][3] * inv1, hi, lo);
        *(uint32_t*)(g_ch + base1 + d) = hi;
        *(uint32_t*)(g_cl + base1 + d) = lo;
    }
}

// ---------------------------------------------------------------------------
extern "C" void kernel_launch(void* const* d_in, const int* in_sizes, int n_in,
                              void* d_out, int out_size) {
    (void)in_sizes; (void)n_in; (void)out_size;
    const float* q    = (const float*)d_in[0];
    const float* k    = (const float*)d_in[1];
    const float* v    = (const float*)d_in[2];
    const int*   mask = (const int*)d_in[3];
    const float* Wq = (const float*)d_in[4];
    const float* bq = (const float*)d_in[5];
    const float* Wk = (const float*)d_in[6];
    const float* bk = (const float*)d_in[7];
    const float* Wv = (const float*)d_in[8];
    const float* bv = (const float*)d_in[9];
    const float* Wo = (const float*)d_in[10];
    const float* bo = (const float*)d_in[11];
    float* out = (float*)d_out;

    cudaFuncSetAttribute(gemm_bf3, cudaFuncAttributeMaxDynamicSharedMemorySize, SM_BYTES);
    cudaFuncSetAttribute(flash_attn, cudaFuncAttributeMaxDynamicSharedMemorySize, F_SMEM);

    cvt_split<<<(MTOT * DM) / (256 * 4), 256>>>(q, 0);
    cvt_split<<<(MTOT * DM) / (256 * 4), 256>>>(k, 1);
    cvt_split<<<(MTOT * DM) / (256 * 4), 256>>>(v, 2);
    dim3 tB(32, 8), tG(DM / 32, DM / 32);
    cvt_wT<<<tG, tB>>>(Wq, 0);
    cvt_wT<<<tG, tB>>>(Wk, 1);
    cvt_wT<<<tG, tB>>>(Wv, 2);
    cvt_wT<<<tG, tB>>>(Wo, 3);
    pack_mask<<<(BSZ * SEQL * SEQL) / (256 * 4), 256>>>(mask);

    dim3 gg(DM / 128, MTOT / 128);
    gemm_bf3<<<gg, 256, SM_BYTES>>>(0, bq, nullptr);
    gemm_bf3<<<gg, 256, SM_BYTES>>>(1, bk, nullptr);
    gemm_bf3<<<gg, 256, SM_BYTES>>>(2, bv, nullptr);

    dim3 gf(SEQL / 128, BSZ * H_);
    flash_attn<<<gf, 256, F_SMEM>>>();

    gemm_bf3<<<gg, 256, SM_BYTES>>>(3, bo, out);
}

// round 5
// speedup vs baseline: 3.5768x; 1.1570x over previous
#include <cuda_runtime.h>
#include <cuda_bf16.h>
#include <cuda_fp16.h>
#include <cstdint>

// Problem constants
constexpr int H_   = 16;
constexpr int DM   = 1024;
constexpr int DK   = 64;
constexpr int BSZ  = 8;
constexpr int SEQL = 1024;
constexpr int MTOT = BSZ * SEQL;   // 8192

// ---------------------------------------------------------------------------
// Device scratch
// ---------------------------------------------------------------------------
// bf16 split activations (hi/lo): [8192,1024]
__device__ __align__(16) __nv_bfloat16 g_qah[(size_t)MTOT * DM], g_qal[(size_t)MTOT * DM];
__device__ __align__(16) __nv_bfloat16 g_kah[(size_t)MTOT * DM], g_kal[(size_t)MTOT * DM];
__device__ __align__(16) __nv_bfloat16 g_vah[(size_t)MTOT * DM], g_val_[(size_t)MTOT * DM];
// transposed weights [N,K] bf16 hi/lo
__device__ __align__(16) __nv_bfloat16 g_wqh[(size_t)DM * DM], g_wql[(size_t)DM * DM];
__device__ __align__(16) __nv_bfloat16 g_wkh[(size_t)DM * DM], g_wkl[(size_t)DM * DM];
__device__ __align__(16) __nv_bfloat16 g_wvh[(size_t)DM * DM], g_wvl[(size_t)DM * DM];
__device__ __align__(16) __nv_bfloat16 g_woh[(size_t)DM * DM], g_wol[(size_t)DM * DM];
// head-layout projected Q/K/V fp16 single: [b*H+h][s][d]
__device__ __align__(16) __half g_qhf[(size_t)BSZ * H_ * SEQL * DK];
__device__ __align__(16) __half g_khf[(size_t)BSZ * H_ * SEQL * DK];
__device__ __align__(16) __half g_vhf[(size_t)BSZ * H_ * SEQL * DK];
// concat(ctx) bf16 hi/lo [8192,1024]
__device__ __align__(16) __nv_bfloat16 g_ch[(size_t)MTOT * DM], g_cl[(size_t)MTOT * DM];
// bit-packed mask [b][q][k/32]
__device__ __align__(16) uint32_t g_mb[(size_t)BSZ * SEQL * (SEQL / 32)];

// ---------------------------------------------------------------------------
// helpers
// ---------------------------------------------------------------------------
__device__ __forceinline__ uint32_t smem_u32(const void* p) {
    uint32_t a;
    asm("{ .reg .u64 t; cvta.to.shared.u64 t, %1; cvt.u32.u64 %0, t; }"
        : "=r"(a) : "l"(p));
    return a;
}
#define SWZ(o) ((o) ^ (((o) >> 3) & 0x70))

__device__ __forceinline__ void ldsm_x4(uint32_t r[4], uint32_t a) {
    asm volatile("ldmatrix.sync.aligned.m8n8.x4.shared.b16 {%0,%1,%2,%3}, [%4];"
                 : "=r"(r[0]), "=r"(r[1]), "=r"(r[2]), "=r"(r[3]) : "r"(a));
}
__device__ __forceinline__ void ldsm_x4_t(uint32_t r[4], uint32_t a) {
    asm volatile("ldmatrix.sync.aligned.m8n8.x4.trans.shared.b16 {%0,%1,%2,%3}, [%4];"
                 : "=r"(r[0]), "=r"(r[1]), "=r"(r[2]), "=r"(r[3]) : "r"(a));
}
__device__ __forceinline__ void mma_bf16(float c[4], const uint32_t a[4], const uint32_t b[2]) {
    asm volatile(
        "mma.sync.aligned.m16n8k16.row.col.f32.bf16.bf16.f32 "
        "{%0,%1,%2,%3}, {%4,%5,%6,%7}, {%8,%9}, {%0,%1,%2,%3};"
        : "+f"(c[0]), "+f"(c[1]), "+f"(c[2]), "+f"(c[3])
        : "r"(a[0]), "r"(a[1]), "r"(a[2]), "r"(a[3]), "r"(b[0]), "r"(b[1]));
}
__device__ __forceinline__ void mma_f16(float c[4], const uint32_t a[4], const uint32_t b[2]) {
    asm volatile(
        "mma.sync.aligned.m16n8k16.row.col.f32.f16.f16.f32 "
        "{%0,%1,%2,%3}, {%4,%5,%6,%7}, {%8,%9}, {%0,%1,%2,%3};"
        : "+f"(c[0]), "+f"(c[1]), "+f"(c[2]), "+f"(c[3])
        : "r"(a[0]), "r"(a[1]), "r"(a[2]), "r"(a[3]), "r"(b[0]), "r"(b[1]));
}
#define CP16(s, g) \
    asm volatile("cp.async.cg.shared.global [%0], [%1], 16;" :: "r"(s), "l"(g))
#define CP_COMMIT() asm volatile("cp.async.commit_group;" ::: "memory")
#define CP_WAIT1()  asm volatile("cp.async.wait_group 1;" ::: "memory")

__device__ __forceinline__ void split2(float x, float y, uint32_t& hi, uint32_t& lo) {
    __nv_bfloat16 hx = __float2bfloat16(x), hy = __float2bfloat16(y);
    __nv_bfloat16 lx = __float2bfloat16(x - __bfloat162float(hx));
    __nv_bfloat16 ly = __float2bfloat16(y - __bfloat162float(hy));
    __nv_bfloat162 Hh = __halves2bfloat162(hx, hy), Ll = __halves2bfloat162(lx, ly);
    hi = *(uint32_t*)&Hh; lo = *(uint32_t*)&Ll;
}
__device__ __forceinline__ uint32_t f2h2(float x, float y) {
    float2 f; f.x = x; f.y = y;
    __half2 h = __float22half2_rn(f);
    return *(uint32_t*)&h;
}

// ---------------------------------------------------------------------------
// Prep kernels
// ---------------------------------------------------------------------------
__global__ __launch_bounds__(256) void cvt_split(const float* __restrict__ X, int sel) {
    __nv_bfloat16 *Hh, *Ll;
    if (sel == 0) { Hh = g_qah; Ll = g_qal; }
    else if (sel == 1) { Hh = g_kah; Ll = g_kal; }
    else { Hh = g_vah; Ll = g_val_; }
    size_t i = ((size_t)blockIdx.x * 256 + threadIdx.x) * 4;
    float4 v = *(const float4*)(X + i);
    __nv_bfloat16 h0 = __float2bfloat16(v.x), h1 = __float2bfloat16(v.y);
    __nv_bfloat16 h2 = __float2bfloat16(v.z), h3 = __float2bfloat16(v.w);
    __nv_bfloat16 l0 = __float2bfloat16(v.x - __bfloat162float(h0));
    __nv_bfloat16 l1 = __float2bfloat16(v.y - __bfloat162float(h1));
    __nv_bfloat16 l2 = __float2bfloat16(v.z - __bfloat162float(h2));
    __nv_bfloat16 l3 = __float2bfloat16(v.w - __bfloat162float(h3));
    *(__nv_bfloat162*)(Hh + i)     = __halves2bfloat162(h0, h1);
    *(__nv_bfloat162*)(Hh + i + 2) = __halves2bfloat162(h2, h3);
    *(__nv_bfloat162*)(Ll + i)     = __halves2bfloat162(l0, l1);
    *(__nv_bfloat162*)(Ll + i + 2) = __halves2bfloat162(l2, l3);
}

__global__ __launch_bounds__(256) void cvt_wT(const float* __restrict__ W, int sel) {
    __nv_bfloat16 *Hh, *Ll;
    if (sel == 0) { Hh = g_wqh; Ll = g_wql; }
    else if (sel == 1) { Hh = g_wkh; Ll = g_wkl; }
    else if (sel == 2) { Hh = g_wvh; Ll = g_wvl; }
    else { Hh = g_woh; Ll = g_wol; }
    __shared__ float t[32][33];
    int x = blockIdx.x * 32 + threadIdx.x;   // n
    int y = blockIdx.y * 32 + threadIdx.y;   // k
    #pragma unroll
    for (int j = 0; j < 32; j += 8)
        t[threadIdx.y + j][threadIdx.x] = W[(size_t)(y + j) * DM + x];
    __syncthreads();
    int xo = blockIdx.y * 32 + threadIdx.x;  // k
    int yo = blockIdx.x * 32 + threadIdx.y;  // n
    #pragma unroll
    for (int j = 0; j < 32; j += 8) {
        float v = t[threadIdx.x][threadIdx.y + j];
        __nv_bfloat16 h = __float2bfloat16(v);
        __nv_bfloat16 l = __float2bfloat16(v - __bfloat162float(h));
        Hh[(size_t)(yo + j) * DM + xo] = h;
        Ll[(size_t)(yo + j) * DM + xo] = l;
    }
}

// bit-pack mask: warp w produces word w via ballot
__global__ __launch_bounds__(256) void pack_mask_bits(const int* __restrict__ m) {
    size_t gw = (size_t)blockIdx.x * 8 + (threadIdx.x >> 5);   // global word id
    int lane = threadIdx.x & 31;
    int v = m[gw * 32 + lane];
    uint32_t bits = __ballot_sync(0xffffffffu, v != 0);
    if (lane == 0) g_mb[gw] = bits;
}

// ---------------------------------------------------------------------------
// HMMA split-bf16 GEMM. sel 0/1/2 -> fp16 head layout (Q scaled 0.125);
// sel 3 -> fp32 flat output.
// ---------------------------------------------------------------------------
constexpr int SM_STAGE = 32768;
constexpr int SM_BYTES = 2 * SM_STAGE;

extern __shared__ char dsm[];

__device__ __forceinline__ void issue_stage(
    uint32_t sbase, int stage,
    const __nv_bfloat16* __restrict__ Ah, const __nv_bfloat16* __restrict__ Al,
    const __nv_bfloat16* __restrict__ Bh, const __nv_bfloat16* __restrict__ Bl,
    int m0, int n0, int kc, int tid)
{
    uint32_t sa = sbase + stage * SM_STAGE;
    uint32_t sbB = sa + 16384;
    #pragma unroll
    for (int i = 0; i < 4; ++i) {
        int idx = tid + (i << 8);
        int row = idx >> 3, c = idx & 7;
        uint32_t so = SWZ(row * 128 + c * 16);
        const __nv_bfloat16* srcA = (c < 4)
            ? (Ah + ((size_t)(m0 + row) << 10) + kc + (c << 3))
            : (Al + ((size_t)(m0 + row) << 10) + kc + ((c - 4) << 3));
        CP16(sa + so, srcA);
        const __nv_bfloat16* srcB = (c < 4)
            ? (Bh + ((size_t)(n0 + row) << 10) + kc + (c << 3))
            : (Bl + ((size_t)(n0 + row) << 10) + kc + ((c - 4) << 3));
        CP16(sbB + so, srcB);
    }
}

__global__ __launch_bounds__(256) void gemm_bf3(int sel, const float* __restrict__ bias,
                                                float* __restrict__ outF) {
    const __nv_bfloat16 *Ah, *Al, *Bh, *Bl;
    __half* OF = nullptr;
    if (sel == 0) { Ah = g_qah; Al = g_qal; Bh = g_wqh; Bl = g_wql; OF = g_qhf; }
    else if (sel == 1) { Ah = g_kah; Al = g_kal; Bh = g_wkh; Bl = g_wkl; OF = g_khf; }
    else if (sel == 2) { Ah = g_vah; Al = g_val_; Bh = g_wvh; Bl = g_wvl; OF = g_vhf; }
    else { Ah = g_ch; Al = g_cl; Bh = g_woh; Bl = g_wol; }

    const uint32_t sbase = smem_u32(dsm);
    const int tid = threadIdx.x, lane = tid & 31, wid = tid >> 5;
    const int wm = wid >> 2, wn = wid & 3;
    const int m0 = blockIdx.y << 7, n0 = blockIdx.x << 7;
    const int lrow = lane & 15, lchunk = lane >> 4;

    float acc[4][4][4] = {};

    issue_stage(sbase, 0, Ah, Al, Bh, Bl, m0, n0, 0, tid);  CP_COMMIT();
    issue_stage(sbase, 1, Ah, Al, Bh, Bl, m0, n0, 32, tid); CP_COMMIT();

    for (int it = 0; it < 32; ++it) {
        CP_WAIT1();
        __syncthreads();
        uint32_t sa = sbase + (it & 1) * SM_STAGE;
        uint32_t sb = sa + 16384;
        #pragma unroll
        for (int s = 0; s < 2; ++s) {
            const int coffH = s * 32 + lchunk * 16;
            const int coffL = 64 + coffH;
            uint32_t aH[4][4];
            #pragma unroll
            for (int f = 0; f < 4; ++f) {
                int r = (wm << 6) + (f << 4) + lrow;
                ldsm_x4(aH[f], sa + SWZ(r * 128 + coffH));
            }
            uint32_t bH[4][2];
            #pragma unroll
            for (int p = 0; p < 2; ++p) {
                int r = (wn << 5) + (p << 4) + lrow;
                uint32_t rr[4];
                ldsm_x4(rr, sb + SWZ(r * 128 + coffH));
                bH[p * 2][0] = rr[0]; bH[p * 2][1] = rr[2];
                bH[p * 2 + 1][0] = rr[1]; bH[p * 2 + 1][1] = rr[3];
            }
            #pragma unroll
            for (int f = 0; f < 4; ++f)
                #pragma unroll
                for (int n = 0; n < 4; ++n)
                    mma_bf16(acc[f][n], aH[f], bH[n]);
            #pragma unroll
            for (int p = 0; p < 2; ++p) {
                int r = (wn << 5) + (p << 4) + lrow;
                uint32_t rr[4];
                ldsm_x4(rr, sb + SWZ(r * 128 + coffL));
                uint32_t bL0[2] = { rr[0], rr[2] };
                uint32_t bL1[2] = { rr[1], rr[3] };
                #pragma unroll
                for (int f = 0; f < 4; ++f) {
                    mma_bf16(acc[f][p * 2], aH[f], bL0);
                    mma_bf16(acc[f][p * 2 + 1], aH[f], bL1);
                }
            }
            #pragma unroll
            for (int f = 0; f < 4; ++f) {
                int r = (wm << 6) + (f << 4) + lrow;
                uint32_t aL[4];
                ldsm_x4(aL, sa + SWZ(r * 128 + coffL));
                #pragma unroll
                for (int n = 0; n < 4; ++n)
                    mma_bf16(acc[f][n], aL, bH[n]);
            }
        }
        __syncthreads();
        int nk = it + 2;
        if (nk < 32)
            issue_stage(sbase, nk & 1, Ah, Al, Bh, Bl, m0, n0, nk * 32, tid);
        CP_COMMIT();
    }

    const int lr = lane >> 2, lc = (lane & 3) << 1;
    const float scale = (sel == 0) ? 0.125f : 1.0f;
    #pragma unroll
    for (int f = 0; f < 4; ++f) {
        #pragma unroll
        for (int half = 0; half < 2; ++half) {
            int m = m0 + (wm << 6) + (f << 4) + lr + (half << 3);
            int b = m >> 10, s = m & 1023;
            #pragma unroll
            for (int n = 0; n < 4; ++n) {
                int ncol = n0 + (wn << 5) + (n << 3) + lc;
                float x0 = acc[f][n][half * 2 + 0] + __ldg(bias + ncol);
                float x1 = acc[f][n][half * 2 + 1] + __ldg(bias + ncol + 1);
                if (sel == 3) {
                    float2 o; o.x = x0; o.y = x1;
                    *(float2*)(outF + (size_t)m * DM + ncol) = o;
                } else {
                    int hh = ncol >> 6, d = ncol & 63;
                    size_t off = ((((size_t)b * H_ + hh) << 10) + s) * DK + d;
                    *(uint32_t*)(OF + off) = f2h2(x0 * scale, x1 * scale);
                }
            }
        }
    }
}

// ---------------------------------------------------------------------------
// Fused flash attention, single-pass fp16 HMMA.
// Grid (8 q-tiles, 128 bh). 256 threads = 8 warps, warp w owns q rows [16w,16w+16).
// ---------------------------------------------------------------------------
constexpr int F_Q   = 0;        // 16 KB (128 x 64 fp16)
constexpr int F_STG = 16384;    // stages follow
constexpr int F_K = 0, F_V = 16384;
constexpr int F_STGSZ = 32768;
constexpr int F_SMEM = F_STG + 2 * F_STGSZ;   // 81920

__device__ __forceinline__ void issue_kv(uint32_t sbase, int stage, int z,
                                         int k0, int tid) {
    uint32_t s = sbase + F_STG + stage * F_STGSZ;
    #pragma unroll
    for (int i = 0; i < 4; ++i) {
        int idx = tid + (i << 8);
        int r = idx >> 3, c = idx & 7;
        uint32_t so = SWZ(r * 128 + c * 16);
        size_t go = ((size_t)z * SEQL + k0 + r) * DK + (c << 3);
        CP16(s + F_K + so, g_khf + go);
        CP16(s + F_V + so, g_vhf + go);
    }
}

__global__ void __launch_bounds__(256, 1) flash_attn() {
    const uint32_t sbase = smem_u32(dsm);
    const int tid = threadIdx.x, lane = tid & 31, w = tid >> 5;
    const int z = blockIdx.y;
    const int b = z >> 4, h = z & 15;
    const int q0 = blockIdx.x << 7;

    // Q tile load
    #pragma unroll
    for (int i = 0; i < 2; ++i) {
        int idx = tid + (i << 8);
        int r = idx >> 2, c = (idx & 3) << 1;
        uint32_t so = SWZ(r * 128 + c * 16);
        size_t go = ((size_t)z * SEQL + q0 + r) * DK + (c << 3);
        CP16(sbase + F_Q + so, g_qhf + go);
        CP16(sbase + F_Q + SWZ(r * 128 + (c + 1) * 16), g_qhf + go + 8);
    }
    CP_COMMIT();
    issue_kv(sbase, 0, z, 0, tid);   CP_COMMIT();
    issue_kv(sbase, 1, z, 128, tid); CP_COMMIT();

    CP_WAIT1();
    __syncthreads();

    // Q fragments held in regs
    uint32_t qf[4][4];
    #pragma unroll
    for (int c = 0; c < 4; ++c) {
        int r = (w << 4) + (lane & 15);
        uint32_t coff = (c << 5) + ((lane >> 4) << 4);
        ldsm_x4(qf[c], sbase + F_Q + SWZ(r * 128 + coff));
    }

    float oacc[8][4] = {};
    float ml0 = -1e30f, ml1 = -1e30f, ll0 = 0.f, ll1 = 0.f;
    const int rql = (w << 4) + (lane >> 2);      // local q row (first of pair)
    const int cb2 = (lane & 3) << 1;
    const uint32_t* mrow0 = g_mb + ((size_t)b * SEQL + q0 + rql) * 32;
    const uint32_t* mrow1 = mrow0 + 8 * 32;

    for (int kt = 0; kt < 8; ++kt) {
        if (kt) { CP_WAIT1(); __syncthreads(); }
        uint32_t s = sbase + F_STG + (kt & 1) * F_STGSZ;

        float sacc[16][4] = {};
        // ---- S = Q K^T ----
        #pragma unroll
        for (int c = 0; c < 4; ++c) {
            #pragma unroll
            for (int p = 0; p < 8; ++p) {
                int r = (p << 4) + (lane & 15);
                uint32_t coff = (c << 5) + ((lane >> 4) << 4);
                uint32_t rh[4];
                ldsm_x4(rh, s + F_K + SWZ(r * 128 + coff));
                uint32_t b0[2] = { rh[0], rh[2] }, b1[2] = { rh[1], rh[3] };
                mma_f16(sacc[2 * p],     qf[c], b0);
                mma_f16(sacc[2 * p + 1], qf[c], b1);
            }
        }

        // ---- mask (bit-packed, global L2) + online softmax ----
        const uint32_t m00 = mrow0[(kt << 2) + 0], m01 = mrow0[(kt << 2) + 1];
        const uint32_t m02 = mrow0[(kt << 2) + 2], m03 = mrow0[(kt << 2) + 3];
        const uint32_t m10 = mrow1[(kt << 2) + 0], m11 = mrow1[(kt << 2) + 1];
        const uint32_t m12 = mrow1[(kt << 2) + 2], m13 = mrow1[(kt << 2) + 3];
        float tm0 = -1e30f, tm1 = -1e30f;
        #pragma unroll
        for (int n = 0; n < 16; ++n) {
            uint32_t w0 = (n < 4) ? m00 : (n < 8) ? m01 : (n < 12) ? m02 : m03;
            uint32_t w1 = (n < 4) ? m10 : (n < 8) ? m11 : (n < 12) ? m12 : m13;
            int bit = ((n & 3) << 3) + cb2;
            float v0 = ((w0 >> bit) & 1u)       ? sacc[n][0] : -1e9f;
            float v1 = ((w0 >> (bit + 1)) & 1u) ? sacc[n][1] : -1e9f;
            float v2 = ((w1 >> bit) & 1u)       ? sacc[n][2] : -1e9f;
            float v3 = ((w1 >> (bit + 1)) & 1u) ? sacc[n][3] : -1e9f;
            sacc[n][0] = v0; sacc[n][1] = v1; sacc[n][2] = v2; sacc[n][3] = v3;
            tm0 = fmaxf(tm0, fmaxf(v0, v1));
            tm1 = fmaxf(tm1, fmaxf(v2, v3));
        }
        tm0 = fmaxf(tm0, __shfl_xor_sync(0xffffffffu, tm0, 1));
        tm0 = fmaxf(tm0, __shfl_xor_sync(0xffffffffu, tm0, 2));
        tm1 = fmaxf(tm1, __shfl_xor_sync(0xffffffffu, tm1, 1));
        tm1 = fmaxf(tm1, __shfl_xor_sync(0xffffffffu, tm1, 2));
        float mn0 = fmaxf(ml0, tm0), mn1 = fmaxf(ml1, tm1);
        float al0 = __expf(ml0 - mn0), al1 = __expf(ml1 - mn1);
        ml0 = mn0; ml1 = mn1;
        float ts0 = 0.f, ts1 = 0.f;
        #pragma unroll
        for (int n = 0; n < 16; ++n) {
            float p0 = __expf(sacc[n][0] - mn0);
            float p1 = __expf(sacc[n][1] - mn0);
            float p2 = __expf(sacc[n][2] - mn1);
            float p3 = __expf(sacc[n][3] - mn1);
            sacc[n][0] = p0; sacc[n][1] = p1; sacc[n][2] = p2; sacc[n][3] = p3;
            ts0 += p0 + p1; ts1 += p2 + p3;
        }
        ts0 += __shfl_xor_sync(0xffffffffu, ts0, 1);
        ts0 += __shfl_xor_sync(0xffffffffu, ts0, 2);
        ts1 += __shfl_xor_sync(0xffffffffu, ts1, 1);
        ts1 += __shfl_xor_sync(0xffffffffu, ts1, 2);
        ll0 = ll0 * al0 + ts0;
        ll1 = ll1 * al1 + ts1;
        #pragma unroll
        for (int nd = 0; nd < 8; ++nd) {
            oacc[nd][0] *= al0; oacc[nd][1] *= al0;
            oacc[nd][2] *= al1; oacc[nd][3] *= al1;
        }

        // ---- O += P V (fp16, V via ldmatrix.trans) ----
        #pragma unroll
        for (int j = 0; j < 8; ++j) {
            uint32_t ap[4];
            ap[0] = f2h2(sacc[2 * j][0],     sacc[2 * j][1]);
            ap[1] = f2h2(sacc[2 * j][2],     sacc[2 * j][3]);
            ap[2] = f2h2(sacc[2 * j + 1][0], sacc[2 * j + 1][1]);
            ap[3] = f2h2(sacc[2 * j + 1][2], sacc[2 * j + 1][3]);
            #pragma unroll
            for (int nd = 0; nd < 4; ++nd) {
                int r = (j << 4) + (lane & 15);
                uint32_t coff = (nd << 5) + ((lane >> 4) << 4);
                uint32_t vh[4];
                ldsm_x4_t(vh, s + F_V + SWZ(r * 128 + coff));
                uint32_t b0[2] = { vh[0], vh[1] }, b1[2] = { vh[2], vh[3] };
                mma_f16(oacc[2 * nd],     ap, b0);
                mma_f16(oacc[2 * nd + 1], ap, b1);
            }
        }

        __syncthreads();
        int nk = kt + 2;
        if (nk < 8) issue_kv(sbase, nk & 1, z, nk << 7, tid);
        CP_COMMIT();
    }

    // ---- epilogue: O/l -> split-bf16 concat ----
    float inv0 = 1.0f / ll0, inv1 = 1.0f / ll1;
    int qr = q0 + rql;
    size_t base0 = (((size_t)b << 10) + qr) * DM + (h << 6);
    size_t base1 = base0 + (size_t)8 * DM;
    #pragma unroll
    for (int nd = 0; nd < 8; ++nd) {
        int d = (nd << 3) + cb2;
        uint32_t hi, lo;
        split2(oacc[nd][0] * inv0, oacc[nd][1] * inv0, hi, lo);
        *(uint32_t*)(g_ch + base0 + d) = hi;
        *(uint32_t*)(g_cl + base0 + d) = lo;
        split2(oacc[nd][2] * inv1, oacc[nd][3] * inv1, hi, lo);
        *(uint32_t*)(g_ch + base1 + d) = hi;
        *(uint32_t*)(g_cl + base1 + d) = lo;
    }
}

// ---------------------------------------------------------------------------
extern "C" void kernel_launch(void* const* d_in, const int* in_sizes, int n_in,
                              void* d_out, int out_size) {
    (void)in_sizes; (void)n_in; (void)out_size;
    const float* q    = (const float*)d_in[0];
    const float* k    = (const float*)d_in[1];
    const float* v    = (const float*)d_in[2];
    const int*   mask = (const int*)d_in[3];
    const float* Wq = (const float*)d_in[4];
    const float* bq = (const float*)d_in[5];
    const float* Wk = (const float*)d_in[6];
    const float* bk = (const float*)d_in[7];
    const float* Wv = (const float*)d_in[8];
    const float* bv = (const float*)d_in[9];
    const float* Wo = (const float*)d_in[10];
    const float* bo = (const float*)d_in[11];
    float* out = (float*)d_out;

    cudaFuncSetAttribute(gemm_bf3, cudaFuncAttributeMaxDynamicSharedMemorySize, SM_BYTES);
    cudaFuncSetAttribute(flash_attn, cudaFuncAttributeMaxDynamicSharedMemorySize, F_SMEM);

    cvt_split<<<(MTOT * DM) / (256 * 4), 256>>>(q, 0);
    cvt_split<<<(MTOT * DM) / (256 * 4), 256>>>(k, 1);
    cvt_split<<<(MTOT * DM) / (256 * 4), 256>>>(v, 2);
    dim3 tB(32, 8), tG(DM / 32, DM / 32);
    cvt_wT<<<tG, tB>>>(Wq, 0);
    cvt_wT<<<tG, tB>>>(Wk, 1);
    cvt_wT<<<tG, tB>>>(Wv, 2);
    cvt_wT<<<tG, tB>>>(Wo, 3);
    pack_mask_bits<<<(BSZ * SEQL * SEQL / 32) / 8, 256>>>(mask);

    dim3 gg(DM / 128, MTOT / 128);
    gemm_bf3<<<gg, 256, SM_BYTES>>>(0, bq, nullptr);
    gemm_bf3<<<gg, 256, SM_BYTES>>>(1, bk, nullptr);
    gemm_bf3<<<gg, 256, SM_BYTES>>>(2, bv, nullptr);

    dim3 gf(SEQL / 128, BSZ * H_);
    flash_attn<<<gf, 256, F_SMEM>>>();

    gemm_bf3<<<gg, 256, SM_BYTES>>>(3, bo, out);
}

// round 6
// speedup vs baseline: 5.2244x; 1.4606x over previous
#include <cuda_runtime.h>
#include <cuda_fp16.h>
#include <cstdint>

// Problem constants
constexpr int H_   = 16;
constexpr int DM   = 1024;
constexpr int DK   = 64;
constexpr int BSZ  = 8;
constexpr int SEQL = 1024;
constexpr int MTOT = BSZ * SEQL;   // 8192

// ---------------------------------------------------------------------------
// Device scratch
// ---------------------------------------------------------------------------
// fp16 activations: [8192,1024]
__device__ __align__(16) __half g_qaf[(size_t)MTOT * DM];
__device__ __align__(16) __half g_kaf[(size_t)MTOT * DM];
__device__ __align__(16) __half g_vaf[(size_t)MTOT * DM];
// transposed weights [N,K] fp16 hi/lo
__device__ __align__(16) __half g_wqh[(size_t)DM * DM], g_wql[(size_t)DM * DM];
__device__ __align__(16) __half g_wkh[(size_t)DM * DM], g_wkl[(size_t)DM * DM];
__device__ __align__(16) __half g_wvh[(size_t)DM * DM], g_wvl[(size_t)DM * DM];
__device__ __align__(16) __half g_woh[(size_t)DM * DM], g_wol[(size_t)DM * DM];
// head-layout projected Q/K/V fp16: [b*H+h][s][d]
__device__ __align__(16) __half g_qhf[(size_t)BSZ * H_ * SEQL * DK];
__device__ __align__(16) __half g_khf[(size_t)BSZ * H_ * SEQL * DK];
__device__ __align__(16) __half g_vhf[(size_t)BSZ * H_ * SEQL * DK];
// concat(ctx) fp16 [8192,1024]
__device__ __align__(16) __half g_chf[(size_t)MTOT * DM];
// bit-packed mask [b][q][k/32]
__device__ __align__(16) uint32_t g_mb[(size_t)BSZ * SEQL * (SEQL / 32)];

// ---------------------------------------------------------------------------
// helpers
// ---------------------------------------------------------------------------
__device__ __forceinline__ uint32_t smem_u32(const void* p) {
    uint32_t a;
    asm("{ .reg .u64 t; cvta.to.shared.u64 t, %1; cvt.u32.u64 %0, t; }"
        : "=r"(a) : "l"(p));
    return a;
}
#define SWZ(o) ((o) ^ (((o) >> 3) & 0x70))

__device__ __forceinline__ void ldsm_x4(uint32_t r[4], uint32_t a) {
    asm volatile("ldmatrix.sync.aligned.m8n8.x4.shared.b16 {%0,%1,%2,%3}, [%4];"
                 : "=r"(r[0]), "=r"(r[1]), "=r"(r[2]), "=r"(r[3]) : "r"(a));
}
__device__ __forceinline__ void ldsm_x4_t(uint32_t r[4], uint32_t a) {
    asm volatile("ldmatrix.sync.aligned.m8n8.x4.trans.shared.b16 {%0,%1,%2,%3}, [%4];"
                 : "=r"(r[0]), "=r"(r[1]), "=r"(r[2]), "=r"(r[3]) : "r"(a));
}
__device__ __forceinline__ void mma_f16(float c[4], const uint32_t a[4], const uint32_t b[2]) {
    asm volatile(
        "mma.sync.aligned.m16n8k16.row.col.f32.f16.f16.f32 "
        "{%0,%1,%2,%3}, {%4,%5,%6,%7}, {%8,%9}, {%0,%1,%2,%3};"
        : "+f"(c[0]), "+f"(c[1]), "+f"(c[2]), "+f"(c[3])
        : "r"(a[0]), "r"(a[1]), "r"(a[2]), "r"(a[3]), "r"(b[0]), "r"(b[1]));
}
#define CP16(s, g) \
    asm volatile("cp.async.cg.shared.global [%0], [%1], 16;" :: "r"(s), "l"(g))
#define CP_COMMIT() asm volatile("cp.async.commit_group;" ::: "memory")
#define CP_WAIT1()  asm volatile("cp.async.wait_group 1;" ::: "memory")

__device__ __forceinline__ uint32_t f2h2(float x, float y) {
    float2 f; f.x = x; f.y = y;
    __half2 h = __float22half2_rn(f);
    return *(uint32_t*)&h;
}

// ---------------------------------------------------------------------------
// Prep kernels
// ---------------------------------------------------------------------------
__global__ __launch_bounds__(256) void cvt_h(const float* __restrict__ X, int sel) {
    __half* O = (sel == 0) ? g_qaf : (sel == 1) ? g_kaf : g_vaf;
    size_t i = ((size_t)blockIdx.x * 256 + threadIdx.x) * 4;
    float4 v = *(const float4*)(X + i);
    *(uint32_t*)(O + i)     = f2h2(v.x, v.y);
    *(uint32_t*)(O + i + 2) = f2h2(v.z, v.w);
}

__global__ __launch_bounds__(256) void cvt_wT(const float* __restrict__ W, int sel) {
    __half *Hh, *Ll;
    if (sel == 0) { Hh = g_wqh; Ll = g_wql; }
    else if (sel == 1) { Hh = g_wkh; Ll = g_wkl; }
    else if (sel == 2) { Hh = g_wvh; Ll = g_wvl; }
    else { Hh = g_woh; Ll = g_wol; }
    __shared__ float t[32][33];
    int x = blockIdx.x * 32 + threadIdx.x;   // n
    int y = blockIdx.y * 32 + threadIdx.y;   // k
    #pragma unroll
    for (int j = 0; j < 32; j += 8)
        t[threadIdx.y + j][threadIdx.x] = W[(size_t)(y + j) * DM + x];
    __syncthreads();
    int xo = blockIdx.y * 32 + threadIdx.x;  // k
    int yo = blockIdx.x * 32 + threadIdx.y;  // n
    #pragma unroll
    for (int j = 0; j < 32; j += 8) {
        float v = t[threadIdx.x][threadIdx.y + j];
        __half h = __float2half_rn(v);
        __half l = __float2half_rn(v - __half2float(h));
        Hh[(size_t)(yo + j) * DM + xo] = h;
        Ll[(size_t)(yo + j) * DM + xo] = l;
    }
}

__global__ __launch_bounds__(256) void pack_mask_bits(const int* __restrict__ m) {
    size_t gw = (size_t)blockIdx.x * 8 + (threadIdx.x >> 5);
    int lane = threadIdx.x & 31;
    int v = m[gw * 32 + lane];
    uint32_t bits = __ballot_sync(0xffffffffu, v != 0);
    if (lane == 0) g_mb[gw] = bits;
}

// ---------------------------------------------------------------------------
// fp16 2-term GEMM: C = A @ (Bh+Bl)^T + bias. A fp16 [M,K], B split fp16 [N,K].
// CTA tile 128x128, KC=64, 2-stage cp.async. 8 warps (2x4), warp tile 64x32.
// sel 0/1/2 -> fp16 head layout (Q scaled 0.125*log2e); sel 3 -> fp32 flat.
// ---------------------------------------------------------------------------
constexpr int G_STGSZ = 49152;              // A 16KB + Bh 16KB + Bl 16KB
constexpr int G_SMEM  = 2 * G_STGSZ;        // 96KB

extern __shared__ char dsm[];

__device__ __forceinline__ void issue_stage2(
    uint32_t sbase, int stage,
    const __half* __restrict__ A,
    const __half* __restrict__ Bh, const __half* __restrict__ Bl,
    int m0, int n0, int kc, int tid)
{
    uint32_t sa  = sbase + stage * G_STGSZ;
    uint32_t sbh = sa + 16384;
    uint32_t sbl = sa + 32768;
    #pragma unroll
    for (int i = 0; i < 4; ++i) {
        int idx = tid + (i << 8);
        int row = idx >> 3, c = idx & 7;
        uint32_t so = SWZ(row * 128 + c * 16);
        CP16(sa  + so, A  + ((size_t)(m0 + row) << 10) + kc + (c << 3));
        CP16(sbh + so, Bh + ((size_t)(n0 + row) << 10) + kc + (c << 3));
        CP16(sbl + so, Bl + ((size_t)(n0 + row) << 10) + kc + (c << 3));
    }
}

__global__ __launch_bounds__(256) void gemm_h2(int sel, const float* __restrict__ bias,
                                               float* __restrict__ outF) {
    const __half *A, *Bh, *Bl;
    __half* OF = nullptr;
    if (sel == 0) { A = g_qaf; Bh = g_wqh; Bl = g_wql; OF = g_qhf; }
    else if (sel == 1) { A = g_kaf; Bh = g_wkh; Bl = g_wkl; OF = g_khf; }
    else if (sel == 2) { A = g_vaf; Bh = g_wvh; Bl = g_wvl; OF = g_vhf; }
    else { A = g_chf; Bh = g_woh; Bl = g_wol; }

    const uint32_t sbase = smem_u32(dsm);
    const int tid = threadIdx.x, lane = tid & 31, wid = tid >> 5;
    const int wm = wid >> 2, wn = wid & 3;
    const int m0 = blockIdx.y << 7, n0 = blockIdx.x << 7;
    const int lrow = lane & 15, lchunk = lane >> 4;

    float acc[4][4][4] = {};

    issue_stage2(sbase, 0, A, Bh, Bl, m0, n0, 0, tid);  CP_COMMIT();
    issue_stage2(sbase, 1, A, Bh, Bl, m0, n0, 64, tid); CP_COMMIT();

    for (int it = 0; it < 16; ++it) {
        CP_WAIT1();
        __syncthreads();
        uint32_t sa  = sbase + (it & 1) * G_STGSZ;
        uint32_t sbh = sa + 16384;
        uint32_t sbl = sa + 32768;
        #pragma unroll
        for (int c = 0; c < 4; ++c) {
            const int coff = (c << 5) + (lchunk << 4);
            uint32_t aF[4][4];
            #pragma unroll
            for (int f = 0; f < 4; ++f) {
                int r = (wm << 6) + (f << 4) + lrow;
                ldsm_x4(aF[f], sa + SWZ(r * 128 + coff));
            }
            uint32_t bH[4][2], bL[4][2];
            #pragma unroll
            for (int p = 0; p < 2; ++p) {
                int r = (wn << 5) + (p << 4) + lrow;
                uint32_t rr[4];
                ldsm_x4(rr, sbh + SWZ(r * 128 + coff));
                bH[p * 2][0] = rr[0]; bH[p * 2][1] = rr[2];
                bH[p * 2 + 1][0] = rr[1]; bH[p * 2 + 1][1] = rr[3];
                ldsm_x4(rr, sbl + SWZ(r * 128 + coff));
                bL[p * 2][0] = rr[0]; bL[p * 2][1] = rr[2];
                bL[p * 2 + 1][0] = rr[1]; bL[p * 2 + 1][1] = rr[3];
            }
            #pragma unroll
            for (int f = 0; f < 4; ++f)
                #pragma unroll
                for (int n = 0; n < 4; ++n) {
                    mma_f16(acc[f][n], aF[f], bH[n]);
                    mma_f16(acc[f][n], aF[f], bL[n]);
                }
        }
        __syncthreads();
        int nk = it + 2;
        if (nk < 16)
            issue_stage2(sbase, nk & 1, A, Bh, Bl, m0, n0, nk * 64, tid);
        CP_COMMIT();
    }

    const int lr = lane >> 2, lc = (lane & 3) << 1;
    // Q gets 0.125 * log2(e) so flash can use exp2f directly
    const float scale = (sel == 0) ? 0.125f * 1.44269504f : 1.0f;
    #pragma unroll
    for (int f = 0; f < 4; ++f) {
        #pragma unroll
        for (int half = 0; half < 2; ++half) {
            int m = m0 + (wm << 6) + (f << 4) + lr + (half << 3);
            int b = m >> 10, s = m & 1023;
            #pragma unroll
            for (int n = 0; n < 4; ++n) {
                int ncol = n0 + (wn << 5) + (n << 3) + lc;
                float x0 = acc[f][n][half * 2 + 0] + __ldg(bias + ncol);
                float x1 = acc[f][n][half * 2 + 1] + __ldg(bias + ncol + 1);
                if (sel == 3) {
                    float2 o; o.x = x0; o.y = x1;
                    *(float2*)(outF + (size_t)m * DM + ncol) = o;
                } else {
                    int hh = ncol >> 6, d = ncol & 63;
                    size_t off = ((((size_t)b * H_ + hh) << 10) + s) * DK + d;
                    *(uint32_t*)(OF + off) = f2h2(x0 * scale, x1 * scale);
                }
            }
        }
    }
}

// ---------------------------------------------------------------------------
// Fused flash attention, fp16 HMMA, K-tile 64, 16 iters, 2 CTAs/SM.
// Grid (8 q-tiles, 128 bh). 256 threads = 8 warps, warp w owns q rows [16w,16w+16).
// ---------------------------------------------------------------------------
constexpr int F_Q   = 0;        // 16 KB (128 x 64 fp16)
constexpr int F_STG = 16384;
constexpr int F_K = 0, F_V = 8192;
constexpr int F_STGSZ = 16384;  // K 8KB + V 8KB
constexpr int F_SMEM = F_STG + 2 * F_STGSZ;   // 49152

__device__ __forceinline__ void issue_kv(uint32_t sbase, int stage, int z,
                                         int k0, int tid) {
    uint32_t s = sbase + F_STG + stage * F_STGSZ;
    #pragma unroll
    for (int i = 0; i < 2; ++i) {
        int idx = tid + (i << 8);
        int r = idx >> 3, c = idx & 7;
        uint32_t so = SWZ(r * 128 + c * 16);
        size_t go = ((size_t)z * SEQL + k0 + r) * DK + (c << 3);
        CP16(s + F_K + so, g_khf + go);
        CP16(s + F_V + so, g_vhf + go);
    }
}

__global__ void __launch_bounds__(256, 2) flash_attn() {
    const uint32_t sbase = smem_u32(dsm);
    const int tid = threadIdx.x, lane = tid & 31, w = tid >> 5;
    const int z = blockIdx.y;
    const int b = z >> 4, h = z & 15;
    const int q0 = blockIdx.x << 7;

    // Q tile load (128 rows x 128B)
    #pragma unroll
    for (int i = 0; i < 4; ++i) {
        int idx = tid + (i << 8);
        int r = idx >> 3, c = idx & 7;
        uint32_t so = SWZ(r * 128 + c * 16);
        size_t go = ((size_t)z * SEQL + q0 + r) * DK + (c << 3);
        CP16(sbase + F_Q + so, g_qhf + go);
    }
    CP_COMMIT();
    issue_kv(sbase, 0, z, 0, tid);  CP_COMMIT();
    issue_kv(sbase, 1, z, 64, tid); CP_COMMIT();

    CP_WAIT1();
    __syncthreads();

    // Q fragments held in regs
    uint32_t qf[4][4];
    #pragma unroll
    for (int c = 0; c < 4; ++c) {
        int r = (w << 4) + (lane & 15);
        uint32_t coff = (c << 5) + ((lane >> 4) << 4);
        ldsm_x4(qf[c], sbase + F_Q + SWZ(r * 128 + coff));
    }

    float oacc[8][4] = {};
    float ml0 = -1e30f, ml1 = -1e30f, ll0 = 0.f, ll1 = 0.f;
    const int rql = (w << 4) + (lane >> 2);
    const int cb2 = (lane & 3) << 1;
    const uint32_t* mrow0 = g_mb + ((size_t)b * SEQL + q0 + rql) * 32;
    const uint32_t* mrow1 = mrow0 + 8 * 32;

    for (int kt = 0; kt < 16; ++kt) {
        if (kt) { CP_WAIT1(); __syncthreads(); }
        uint32_t s = sbase + F_STG + (kt & 1) * F_STGSZ;

        float sacc[8][4] = {};
        // ---- S = Q K^T (scores already in log2 domain via Q scale) ----
        #pragma unroll
        for (int c = 0; c < 4; ++c) {
            #pragma unroll
            for (int p = 0; p < 4; ++p) {
                int r = (p << 4) + (lane & 15);
                uint32_t coff = (c << 5) + ((lane >> 4) << 4);
                uint32_t rh[4];
                ldsm_x4(rh, s + F_K + SWZ(r * 128 + coff));
                uint32_t b0[2] = { rh[0], rh[2] }, b1[2] = { rh[1], rh[3] };
                mma_f16(sacc[2 * p],     qf[c], b0);
                mma_f16(sacc[2 * p + 1], qf[c], b1);
            }
        }

        // ---- mask (bit-packed) + online softmax (base-2) ----
        const uint32_t m00 = mrow0[(kt << 1) + 0], m01 = mrow0[(kt << 1) + 1];
        const uint32_t m10 = mrow1[(kt << 1) + 0], m11 = mrow1[(kt << 1) + 1];
        float tm0 = -1e30f, tm1 = -1e30f;
        #pragma unroll
        for (int n = 0; n < 8; ++n) {
            uint32_t w0 = (n < 4) ? m00 : m01;
            uint32_t w1 = (n < 4) ? m10 : m11;
            int bit = ((n & 3) << 3) + cb2;
            float v0 = ((w0 >> bit) & 1u)       ? sacc[n][0] : -1e9f;
            float v1 = ((w0 >> (bit + 1)) & 1u) ? sacc[n][1] : -1e9f;
            float v2 = ((w1 >> bit) & 1u)       ? sacc[n][2] : -1e9f;
            float v3 = ((w1 >> (bit + 1)) & 1u) ? sacc[n][3] : -1e9f;
            sacc[n][0] = v0; sacc[n][1] = v1; sacc[n][2] = v2; sacc[n][3] = v3;
            tm0 = fmaxf(tm0, fmaxf(v0, v1));
            tm1 = fmaxf(tm1, fmaxf(v2, v3));
        }
        tm0 = fmaxf(tm0, __shfl_xor_sync(0xffffffffu, tm0, 1));
        tm0 = fmaxf(tm0, __shfl_xor_sync(0xffffffffu, tm0, 2));
        tm1 = fmaxf(tm1, __shfl_xor_sync(0xffffffffu, tm1, 1));
        tm1 = fmaxf(tm1, __shfl_xor_sync(0xffffffffu, tm1, 2));
        float mn0 = fmaxf(ml0, tm0), mn1 = fmaxf(ml1, tm1);
        float al0 = exp2f(ml0 - mn0), al1 = exp2f(ml1 - mn1);
        ml0 = mn0; ml1 = mn1;
        float ts0 = 0.f, ts1 = 0.f;
        #pragma unroll
        for (int n = 0; n < 8; ++n) {
            float p0 = exp2f(sacc[n][0] - mn0);
            float p1 = exp2f(sacc[n][1] - mn0);
            float p2 = exp2f(sacc[n][2] - mn1);
            float p3 = exp2f(sacc[n][3] - mn1);
            sacc[n][0] = p0; sacc[n][1] = p1; sacc[n][2] = p2; sacc[n][3] = p3;
            ts0 += p0 + p1; ts1 += p2 + p3;
        }
        ts0 += __shfl_xor_sync(0xffffffffu, ts0, 1);
        ts0 += __shfl_xor_sync(0xffffffffu, ts0, 2);
        ts1 += __shfl_xor_sync(0xffffffffu, ts1, 1);
        ts1 += __shfl_xor_sync(0xffffffffu, ts1, 2);
        ll0 = ll0 * al0 + ts0;
        ll1 = ll1 * al1 + ts1;
        #pragma unroll
        for (int nd = 0; nd < 8; ++nd) {
            oacc[nd][0] *= al0; oacc[nd][1] *= al0;
            oacc[nd][2] *= al1; oacc[nd][3] *= al1;
        }

        // ---- O += P V (V via ldmatrix.trans) ----
        #pragma unroll
        for (int j = 0; j < 4; ++j) {
            uint32_t ap[4];
            ap[0] = f2h2(sacc[2 * j][0],     sacc[2 * j][1]);
            ap[1] = f2h2(sacc[2 * j][2],     sacc[2 * j][3]);
            ap[2] = f2h2(sacc[2 * j + 1][0], sacc[2 * j + 1][1]);
            ap[3] = f2h2(sacc[2 * j + 1][2], sacc[2 * j + 1][3]);
            #pragma unroll
            for (int nd = 0; nd < 4; ++nd) {
                int r = (j << 4) + (lane & 15);
                uint32_t coff = (nd << 5) + ((lane >> 4) << 4);
                uint32_t vh[4];
                ldsm_x4_t(vh, s + F_V + SWZ(r * 128 + coff));
                uint32_t b0[2] = { vh[0], vh[1] }, b1[2] = { vh[2], vh[3] };
                mma_f16(oacc[2 * nd],     ap, b0);
                mma_f16(oacc[2 * nd + 1], ap, b1);
            }
        }

        __syncthreads();
        int nk = kt + 2;
        if (nk < 16) issue_kv(sbase, nk & 1, z, nk << 6, tid);
        CP_COMMIT();
    }

    // ---- epilogue: O/l -> fp16 concat ----
    float inv0 = 1.0f / ll0, inv1 = 1.0f / ll1;
    int qr = q0 + rql;
    size_t base0 = (((size_t)b << 10) + qr) * DM + (h << 6);
    size_t base1 = base0 + (size_t)8 * DM;
    #pragma unroll
    for (int nd = 0; nd < 8; ++nd) {
        int d = (nd << 3) + cb2;
        *(uint32_t*)(g_chf + base0 + d) = f2h2(oacc[nd][0] * inv0, oacc[nd][1] * inv0);
        *(uint32_t*)(g_chf + base1 + d) = f2h2(oacc[nd][2] * inv1, oacc[nd][3] * inv1);
    }
}

// ---------------------------------------------------------------------------
extern "C" void kernel_launch(void* const* d_in, const int* in_sizes, int n_in,
                              void* d_out, int out_size) {
    (void)in_sizes; (void)n_in; (void)out_size;
    const float* q    = (const float*)d_in[0];
    const float* k    = (const float*)d_in[1];
    const float* v    = (const float*)d_in[2];
    const int*   mask = (const int*)d_in[3];
    const float* Wq = (const float*)d_in[4];
    const float* bq = (const float*)d_in[5];
    const float* Wk = (const float*)d_in[6];
    const float* bk = (const float*)d_in[7];
    const float* Wv = (const float*)d_in[8];
    const float* bv = (const float*)d_in[9];
    const float* Wo = (const float*)d_in[10];
    const float* bo = (const float*)d_in[11];
    float* out = (float*)d_out;

    cudaFuncSetAttribute(gemm_h2, cudaFuncAttributeMaxDynamicSharedMemorySize, G_SMEM);
    cudaFuncSetAttribute(flash_attn, cudaFuncAttributeMaxDynamicSharedMemorySize, F_SMEM);

    cvt_h<<<(MTOT * DM) / (256 * 4), 256>>>(q, 0);
    cvt_h<<<(MTOT * DM) / (256 * 4), 256>>>(k, 1);
    cvt_h<<<(MTOT * DM) / (256 * 4), 256>>>(v, 2);
    dim3 tB(32, 8), tG(DM / 32, DM / 32);
    cvt_wT<<<tG, tB>>>(Wq, 0);
    cvt_wT<<<tG, tB>>>(Wk, 1);
    cvt_wT<<<tG, tB>>>(Wv, 2);
    cvt_wT<<<tG, tB>>>(Wo, 3);
    pack_mask_bits<<<(BSZ * SEQL * SEQL / 32) / 8, 256>>>(mask);

    dim3 gg(DM / 128, MTOT / 128);
    gemm_h2<<<gg, 256, G_SMEM>>>(0, bq, nullptr);
    gemm_h2<<<gg, 256, G_SMEM>>>(1, bk, nullptr);
    gemm_h2<<<gg, 256, G_SMEM>>>(2, bv, nullptr);

    dim3 gf(SEQL / 128, BSZ * H_);
    flash_attn<<<gf, 256, F_SMEM>>>();

    gemm_h2<<<gg, 256, G_SMEM>>>(3, bo, out);
}

// round 7
// speedup vs baseline: 6.8217x; 1.3057x over previous
#include <cuda_runtime.h>
#include <cuda_fp16.h>
#include <cstdint>

// Problem constants
constexpr int H_   = 16;
constexpr int DM   = 1024;
constexpr int DK   = 64;
constexpr int BSZ  = 8;
constexpr int SEQL = 1024;
constexpr int MTOT = BSZ * SEQL;   // 8192

// ---------------------------------------------------------------------------
// Device scratch
// ---------------------------------------------------------------------------
__device__ __align__(16) __half g_qaf[(size_t)MTOT * DM];
__device__ __align__(16) __half g_kaf[(size_t)MTOT * DM];
__device__ __align__(16) __half g_vaf[(size_t)MTOT * DM];
// transposed weights [N,K] fp16 (hi only for QKV; hi+lo for Wo)
__device__ __align__(16) __half g_wqh[(size_t)DM * DM];
__device__ __align__(16) __half g_wkh[(size_t)DM * DM];
__device__ __align__(16) __half g_wvh[(size_t)DM * DM];
__device__ __align__(16) __half g_woh[(size_t)DM * DM], g_wol[(size_t)DM * DM];
// head-layout projected Q/K/V fp16: [b*H+h][s][d]
__device__ __align__(16) __half g_qhf[(size_t)BSZ * H_ * SEQL * DK];
__device__ __align__(16) __half g_khf[(size_t)BSZ * H_ * SEQL * DK];
__device__ __align__(16) __half g_vhf[(size_t)BSZ * H_ * SEQL * DK];
// concat(ctx) fp16 [8192,1024]
__device__ __align__(16) __half g_chf[(size_t)MTOT * DM];
// bit-packed mask [b][q][k/32]
__device__ __align__(16) uint32_t g_mb[(size_t)BSZ * SEQL * (SEQL / 32)];

// ---------------------------------------------------------------------------
// helpers
// ---------------------------------------------------------------------------
__device__ __forceinline__ uint32_t smem_u32(const void* p) {
    uint32_t a;
    asm("{ .reg .u64 t; cvta.to.shared.u64 t, %1; cvt.u32.u64 %0, t; }"
        : "=r"(a) : "l"(p));
    return a;
}
#define SWZ(o) ((o) ^ (((o) >> 3) & 0x70))

__device__ __forceinline__ void ldsm_x4(uint32_t r[4], uint32_t a) {
    asm volatile("ldmatrix.sync.aligned.m8n8.x4.shared.b16 {%0,%1,%2,%3}, [%4];"
                 : "=r"(r[0]), "=r"(r[1]), "=r"(r[2]), "=r"(r[3]) : "r"(a));
}
__device__ __forceinline__ void ldsm_x4_t(uint32_t r[4], uint32_t a) {
    asm volatile("ldmatrix.sync.aligned.m8n8.x4.trans.shared.b16 {%0,%1,%2,%3}, [%4];"
                 : "=r"(r[0]), "=r"(r[1]), "=r"(r[2]), "=r"(r[3]) : "r"(a));
}
__device__ __forceinline__ void mma_f16(float c[4], const uint32_t a[4], const uint32_t b[2]) {
    asm volatile(
        "mma.sync.aligned.m16n8k16.row.col.f32.f16.f16.f32 "
        "{%0,%1,%2,%3}, {%4,%5,%6,%7}, {%8,%9}, {%0,%1,%2,%3};"
        : "+f"(c[0]), "+f"(c[1]), "+f"(c[2]), "+f"(c[3])
        : "r"(a[0]), "r"(a[1]), "r"(a[2]), "r"(a[3]), "r"(b[0]), "r"(b[1]));
}
#define CP16(s, g) \
    asm volatile("cp.async.cg.shared.global [%0], [%1], 16;" :: "r"(s), "l"(g))
#define CP_COMMIT() asm volatile("cp.async.commit_group;" ::: "memory")
#define CP_WAIT1()  asm volatile("cp.async.wait_group 1;" ::: "memory")

__device__ __forceinline__ uint32_t f2h2(float x, float y) {
    float2 f; f.x = x; f.y = y;
    __half2 h = __float22half2_rn(f);
    return *(uint32_t*)&h;
}

// ---------------------------------------------------------------------------
// Prep kernels (merged launches)
// ---------------------------------------------------------------------------
__global__ __launch_bounds__(256) void cvt_h(const float* __restrict__ q,
                                             const float* __restrict__ k,
                                             const float* __restrict__ v) {
    int z = blockIdx.y;
    const float* X = (z == 0) ? q : (z == 1) ? k : v;
    __half* O = (z == 0) ? g_qaf : (z == 1) ? g_kaf : g_vaf;
    size_t i = ((size_t)blockIdx.x * 256 + threadIdx.x) * 4;
    float4 val = *(const float4*)(X + i);
    *(uint32_t*)(O + i)     = f2h2(val.x, val.y);
    *(uint32_t*)(O + i + 2) = f2h2(val.z, val.w);
}

__global__ __launch_bounds__(256) void cvt_wT(const float* __restrict__ Wq,
                                              const float* __restrict__ Wk,
                                              const float* __restrict__ Wv,
                                              const float* __restrict__ Wo) {
    int z = blockIdx.z;
    const float* W = (z == 0) ? Wq : (z == 1) ? Wk : (z == 2) ? Wv : Wo;
    __half* Hh = (z == 0) ? g_wqh : (z == 1) ? g_wkh : (z == 2) ? g_wvh : g_woh;
    __shared__ float t[32][33];
    int x = blockIdx.x * 32 + threadIdx.x;   // n
    int y = blockIdx.y * 32 + threadIdx.y;   // k
    #pragma unroll
    for (int j = 0; j < 32; j += 8)
        t[threadIdx.y + j][threadIdx.x] = W[(size_t)(y + j) * DM + x];
    __syncthreads();
    int xo = blockIdx.y * 32 + threadIdx.x;  // k
    int yo = blockIdx.x * 32 + threadIdx.y;  // n
    #pragma unroll
    for (int j = 0; j < 32; j += 8) {
        float v = t[threadIdx.x][threadIdx.y + j];
        __half h = __float2half_rn(v);
        Hh[(size_t)(yo + j) * DM + xo] = h;
        if (z == 3)
            g_wol[(size_t)(yo + j) * DM + xo] = __float2half_rn(v - __half2float(h));
    }
}

__global__ __launch_bounds__(256) void pack_mask_bits(const int* __restrict__ m) {
    size_t gw = (size_t)blockIdx.x * 8 + (threadIdx.x >> 5);
    int lane = threadIdx.x & 31;
    int v = m[gw * 32 + lane];
    uint32_t bits = __ballot_sync(0xffffffffu, v != 0);
    if (lane == 0) g_mb[gw] = bits;
}

// ---------------------------------------------------------------------------
// QKV projection: single-term fp16 GEMM, 3-stage ring, grid (8, 64, 3).
// CTA tile 128x128, KC=64, 8 warps (2x4), warp tile 64x32.
// ---------------------------------------------------------------------------
constexpr int G1_STGSZ = 32768;              // A 16KB + B 16KB
constexpr int G1_SMEM  = 3 * G1_STGSZ;       // 96KB

extern __shared__ char dsm[];

__device__ __forceinline__ void g1_issue(uint32_t sbase, int stage,
                                         const __half* __restrict__ A,
                                         const __half* __restrict__ B,
                                         int m0, int n0, int kc, int tid)
{
    uint32_t sa = sbase + stage * G1_STGSZ;
    uint32_t sb = sa + 16384;
    #pragma unroll
    for (int i = 0; i < 4; ++i) {
        int idx = tid + (i << 8);
        int row = idx >> 3, c = idx & 7;
        uint32_t so = SWZ(row * 128 + c * 16);
        CP16(sa + so, A + ((size_t)(m0 + row) << 10) + kc + (c << 3));
        CP16(sb + so, B + ((size_t)(n0 + row) << 10) + kc + (c << 3));
    }
}

__global__ __launch_bounds__(256) void gemm_qkv(const float* __restrict__ bq,
                                                const float* __restrict__ bk,
                                                const float* __restrict__ bv) {
    const int z = blockIdx.z;
    const __half* A = (z == 0) ? g_qaf : (z == 1) ? g_kaf : g_vaf;
    const __half* B = (z == 0) ? g_wqh : (z == 1) ? g_wkh : g_wvh;
    const float* bias = (z == 0) ? bq : (z == 1) ? bk : bv;
    __half* OF = (z == 0) ? g_qhf : (z == 1) ? g_khf : g_vhf;

    const uint32_t sbase = smem_u32(dsm);
    const int tid = threadIdx.x, lane = tid & 31, wid = tid >> 5;
    const int wm = wid >> 2, wn = wid & 3;
    const int m0 = blockIdx.y << 7, n0 = blockIdx.x << 7;
    const int lrow = lane & 15, lchunk = lane >> 4;

    float acc[4][4][4] = {};

    g1_issue(sbase, 0, A, B, m0, n0, 0, tid);  CP_COMMIT();
    g1_issue(sbase, 1, A, B, m0, n0, 64, tid); CP_COMMIT();

    for (int it = 0; it < 16; ++it) {
        CP_WAIT1();
        __syncthreads();
        int nk = it + 2;
        if (nk < 16) g1_issue(sbase, nk % 3, A, B, m0, n0, nk * 64, tid);
        CP_COMMIT();
        uint32_t sa = sbase + (it % 3) * G1_STGSZ;
        uint32_t sb = sa + 16384;
        #pragma unroll
        for (int c = 0; c < 4; ++c) {
            const int coff = (c << 5) + (lchunk << 4);
            uint32_t aF[4][4];
            #pragma unroll
            for (int f = 0; f < 4; ++f) {
                int r = (wm << 6) + (f << 4) + lrow;
                ldsm_x4(aF[f], sa + SWZ(r * 128 + coff));
            }
            uint32_t bH[4][2];
            #pragma unroll
            for (int p = 0; p < 2; ++p) {
                int r = (wn << 5) + (p << 4) + lrow;
                uint32_t rr[4];
                ldsm_x4(rr, sb + SWZ(r * 128 + coff));
                bH[p * 2][0] = rr[0]; bH[p * 2][1] = rr[2];
                bH[p * 2 + 1][0] = rr[1]; bH[p * 2 + 1][1] = rr[3];
            }
            #pragma unroll
            for (int f = 0; f < 4; ++f)
                #pragma unroll
                for (int n = 0; n < 4; ++n)
                    mma_f16(acc[f][n], aF[f], bH[n]);
        }
    }

    const int lr = lane >> 2, lc = (lane & 3) << 1;
    const float scale = (z == 0) ? 0.125f * 1.44269504f : 1.0f;
    #pragma unroll
    for (int f = 0; f < 4; ++f) {
        #pragma unroll
        for (int half = 0; half < 2; ++half) {
            int m = m0 + (wm << 6) + (f << 4) + lr + (half << 3);
            int b = m >> 10, s = m & 1023;
            #pragma unroll
            for (int n = 0; n < 4; ++n) {
                int ncol = n0 + (wn << 5) + (n << 3) + lc;
                float x0 = acc[f][n][half * 2 + 0] + __ldg(bias + ncol);
                float x1 = acc[f][n][half * 2 + 1] + __ldg(bias + ncol + 1);
                int hh = ncol >> 6, d = ncol & 63;
                size_t off = ((((size_t)b * H_ + hh) << 10) + s) * DK + d;
                *(uint32_t*)(OF + off) = f2h2(x0 * scale, x1 * scale);
            }
        }
    }
}

// ---------------------------------------------------------------------------
// Output projection: 2-term fp16 GEMM (A fp16, B hi/lo), 2-stage, fp32 out.
// ---------------------------------------------------------------------------
constexpr int G2_STGSZ = 49152;              // A 16KB + Bh 16KB + Bl 16KB
constexpr int G2_SMEM  = 2 * G2_STGSZ;       // 96KB

__device__ __forceinline__ void g2_issue(uint32_t sbase, int stage,
                                         int m0, int n0, int kc, int tid)
{
    uint32_t sa  = sbase + stage * G2_STGSZ;
    uint32_t sbh = sa + 16384;
    uint32_t sbl = sa + 32768;
    #pragma unroll
    for (int i = 0; i < 4; ++i) {
        int idx = tid + (i << 8);
        int row = idx >> 3, c = idx & 7;
        uint32_t so = SWZ(row * 128 + c * 16);
        CP16(sa  + so, g_chf + ((size_t)(m0 + row) << 10) + kc + (c << 3));
        CP16(sbh + so, g_woh + ((size_t)(n0 + row) << 10) + kc + (c << 3));
        CP16(sbl + so, g_wol + ((size_t)(n0 + row) << 10) + kc + (c << 3));
    }
}

__global__ __launch_bounds__(256) void gemm_out(const float* __restrict__ bias,
                                                float* __restrict__ outF) {
    const uint32_t sbase = smem_u32(dsm);
    const int tid = threadIdx.x, lane = tid & 31, wid = tid >> 5;
    const int wm = wid >> 2, wn = wid & 3;
    const int m0 = blockIdx.y << 7, n0 = blockIdx.x << 7;
    const int lrow = lane & 15, lchunk = lane >> 4;

    float acc[4][4][4] = {};

    g2_issue(sbase, 0, m0, n0, 0, tid);  CP_COMMIT();
    g2_issue(sbase, 1, m0, n0, 64, tid); CP_COMMIT();

    for (int it = 0; it < 16; ++it) {
        CP_WAIT1();
        __syncthreads();
        uint32_t sa  = sbase + (it & 1) * G2_STGSZ;
        uint32_t sbh = sa + 16384;
        uint32_t sbl = sa + 32768;
        #pragma unroll
        for (int c = 0; c < 4; ++c) {
            const int coff = (c << 5) + (lchunk << 4);
            uint32_t aF[4][4];
            #pragma unroll
            for (int f = 0; f < 4; ++f) {
                int r = (wm << 6) + (f << 4) + lrow;
                ldsm_x4(aF[f], sa + SWZ(r * 128 + coff));
            }
            uint32_t bH[4][2], bL[4][2];
            #pragma unroll
            for (int p = 0; p < 2; ++p) {
                int r = (wn << 5) + (p << 4) + lrow;
                uint32_t rr[4];
                ldsm_x4(rr, sbh + SWZ(r * 128 + coff));
                bH[p * 2][0] = rr[0]; bH[p * 2][1] = rr[2];
                bH[p * 2 + 1][0] = rr[1]; bH[p * 2 + 1][1] = rr[3];
                ldsm_x4(rr, sbl + SWZ(r * 128 + coff));
                bL[p * 2][0] = rr[0]; bL[p * 2][1] = rr[2];
                bL[p * 2 + 1][0] = rr[1]; bL[p * 2 + 1][1] = rr[3];
            }
            #pragma unroll
            for (int f = 0; f < 4; ++f)
                #pragma unroll
                for (int n = 0; n < 4; ++n) {
                    mma_f16(acc[f][n], aF[f], bH[n]);
                    mma_f16(acc[f][n], aF[f], bL[n]);
                }
        }
        __syncthreads();
        int nk = it + 2;
        if (nk < 16) g2_issue(sbase, nk & 1, m0, n0, nk * 64, tid);
        CP_COMMIT();
    }

    const int lr = lane >> 2, lc = (lane & 3) << 1;
    #pragma unroll
    for (int f = 0; f < 4; ++f) {
        #pragma unroll
        for (int half = 0; half < 2; ++half) {
            int m = m0 + (wm << 6) + (f << 4) + lr + (half << 3);
            #pragma unroll
            for (int n = 0; n < 4; ++n) {
                int ncol = n0 + (wn << 5) + (n << 3) + lc;
                float2 o;
                o.x = acc[f][n][half * 2 + 0] + __ldg(bias + ncol);
                o.y = acc[f][n][half * 2 + 1] + __ldg(bias + ncol + 1);
                *(float2*)(outF + (size_t)m * DM + ncol) = o;
            }
        }
    }
}

// ---------------------------------------------------------------------------
// Fused flash attention, fp16 HMMA, K-tile 64, 3-stage ring, 2 CTAs/SM.
// ---------------------------------------------------------------------------
constexpr int F_Q   = 0;        // 16 KB
constexpr int F_STG = 16384;
constexpr int F_K = 0, F_V = 8192;
constexpr int F_STGSZ = 16384;                 // K 8KB + V 8KB
constexpr int F_SMEM = F_STG + 3 * F_STGSZ;    // 65536

__device__ __forceinline__ void issue_kv(uint32_t sbase, int stage, int z,
                                         int k0, int tid) {
    uint32_t s = sbase + F_STG + stage * F_STGSZ;
    #pragma unroll
    for (int i = 0; i < 2; ++i) {
        int idx = tid + (i << 8);
        int r = idx >> 3, c = idx & 7;
        uint32_t so = SWZ(r * 128 + c * 16);
        size_t go = ((size_t)z * SEQL + k0 + r) * DK + (c << 3);
        CP16(s + F_K + so, g_khf + go);
        CP16(s + F_V + so, g_vhf + go);
    }
}

__global__ void __launch_bounds__(256, 2) flash_attn() {
    const uint32_t sbase = smem_u32(dsm);
    const int tid = threadIdx.x, lane = tid & 31, w = tid >> 5;
    const int z = blockIdx.y;
    const int b = z >> 4, h = z & 15;
    const int q0 = blockIdx.x << 7;

    // Q tile load
    #pragma unroll
    for (int i = 0; i < 4; ++i) {
        int idx = tid + (i << 8);
        int r = idx >> 3, c = idx & 7;
        uint32_t so = SWZ(r * 128 + c * 16);
        size_t go = ((size_t)z * SEQL + q0 + r) * DK + (c << 3);
        CP16(sbase + F_Q + so, g_qhf + go);
    }
    CP_COMMIT();
    issue_kv(sbase, 0, z, 0, tid);  CP_COMMIT();
    issue_kv(sbase, 1, z, 64, tid); CP_COMMIT();

    CP_WAIT1();
    __syncthreads();

    uint32_t qf[4][4];
    #pragma unroll
    for (int c = 0; c < 4; ++c) {
        int r = (w << 4) + (lane & 15);
        uint32_t coff = (c << 5) + ((lane >> 4) << 4);
        ldsm_x4(qf[c], sbase + F_Q + SWZ(r * 128 + coff));
    }

    float oacc[8][4] = {};
    float ml0 = -1e30f, ml1 = -1e30f, ll0 = 0.f, ll1 = 0.f;
    const int rql = (w << 4) + (lane >> 2);
    const int cb2 = (lane & 3) << 1;
    const uint32_t* mrow0 = g_mb + ((size_t)b * SEQL + q0 + rql) * 32;
    const uint32_t* mrow1 = mrow0 + 8 * 32;

    for (int kt = 0; kt < 16; ++kt) {
        if (kt) { CP_WAIT1(); __syncthreads(); }
        int nk = kt + 2;
        if (nk < 16) issue_kv(sbase, nk % 3, z, nk << 6, tid);
        CP_COMMIT();
        uint32_t s = sbase + F_STG + (kt % 3) * F_STGSZ;

        float sacc[8][4] = {};
        // ---- S = Q K^T (log2 domain via Q scale) ----
        #pragma unroll
        for (int c = 0; c < 4; ++c) {
            #pragma unroll
            for (int p = 0; p < 4; ++p) {
                int r = (p << 4) + (lane & 15);
                uint32_t coff = (c << 5) + ((lane >> 4) << 4);
                uint32_t rh[4];
                ldsm_x4(rh, s + F_K + SWZ(r * 128 + coff));
                uint32_t b0[2] = { rh[0], rh[2] }, b1[2] = { rh[1], rh[3] };
                mma_f16(sacc[2 * p],     qf[c], b0);
                mma_f16(sacc[2 * p + 1], qf[c], b1);
            }
        }

        // ---- mask + online softmax (base-2) ----
        const uint32_t m00 = mrow0[(kt << 1) + 0], m01 = mrow0[(kt << 1) + 1];
        const uint32_t m10 = mrow1[(kt << 1) + 0], m11 = mrow1[(kt << 1) + 1];
        float tm0 = -1e30f, tm1 = -1e30f;
        #pragma unroll
        for (int n = 0; n < 8; ++n) {
            uint32_t w0 = (n < 4) ? m00 : m01;
            uint32_t w1 = (n < 4) ? m10 : m11;
            int bit = ((n & 3) << 3) + cb2;
            float v0 = ((w0 >> bit) & 1u)       ? sacc[n][0] : -1e9f;
            float v1 = ((w0 >> (bit + 1)) & 1u) ? sacc[n][1] : -1e9f;
            float v2 = ((w1 >> bit) & 1u)       ? sacc[n][2] : -1e9f;
            float v3 = ((w1 >> (bit + 1)) & 1u) ? sacc[n][3] : -1e9f;
            sacc[n][0] = v0; sacc[n][1] = v1; sacc[n][2] = v2; sacc[n][3] = v3;
            tm0 = fmaxf(tm0, fmaxf(v0, v1));
            tm1 = fmaxf(tm1, fmaxf(v2, v3));
        }
        tm0 = fmaxf(tm0, __shfl_xor_sync(0xffffffffu, tm0, 1));
        tm0 = fmaxf(tm0, __shfl_xor_sync(0xffffffffu, tm0, 2));
        tm1 = fmaxf(tm1, __shfl_xor_sync(0xffffffffu, tm1, 1));
        tm1 = fmaxf(tm1, __shfl_xor_sync(0xffffffffu, tm1, 2));
        float mn0 = fmaxf(ml0, tm0), mn1 = fmaxf(ml1, tm1);
        float al0 = exp2f(ml0 - mn0), al1 = exp2f(ml1 - mn1);
        ml0 = mn0; ml1 = mn1;
        float ts0 = 0.f, ts1 = 0.f;
        #pragma unroll
        for (int n = 0; n < 8; ++n) {
            float p0 = exp2f(sacc[n][0] - mn0);
            float p1 = exp2f(sacc[n][1] - mn0);
            float p2 = exp2f(sacc[n][2] - mn1);
            float p3 = exp2f(sacc[n][3] - mn1);
            sacc[n][0] = p0; sacc[n][1] = p1; sacc[n][2] = p2; sacc[n][3] = p3;
            ts0 += p0 + p1; ts1 += p2 + p3;
        }
        ts0 += __shfl_xor_sync(0xffffffffu, ts0, 1);
        ts0 += __shfl_xor_sync(0xffffffffu, ts0, 2);
        ts1 += __shfl_xor_sync(0xffffffffu, ts1, 1);
        ts1 += __shfl_xor_sync(0xffffffffu, ts1, 2);
        ll0 = ll0 * al0 + ts0;
        ll1 = ll1 * al1 + ts1;
        #pragma unroll
        for (int nd = 0; nd < 8; ++nd) {
            oacc[nd][0] *= al0; oacc[nd][1] *= al0;
            oacc[nd][2] *= al1; oacc[nd][3] *= al1;
        }

        // ---- O += P V ----
        #pragma unroll
        for (int j = 0; j < 4; ++j) {
            uint32_t ap[4];
            ap[0] = f2h2(sacc[2 * j][0],     sacc[2 * j][1]);
            ap[1] = f2h2(sacc[2 * j][2],     sacc[2 * j][3]);
            ap[2] = f2h2(sacc[2 * j + 1][0], sacc[2 * j + 1][1]);
            ap[3] = f2h2(sacc[2 * j + 1][2], sacc[2 * j + 1][3]);
            #pragma unroll
            for (int nd = 0; nd < 4; ++nd) {
                int r = (j << 4) + (lane & 15);
                uint32_t coff = (nd << 5) + ((lane >> 4) << 4);
                uint32_t vh[4];
                ldsm_x4_t(vh, s + F_V + SWZ(r * 128 + coff));
                uint32_t b0[2] = { vh[0], vh[1] }, b1[2] = { vh[2], vh[3] };
                mma_f16(oacc[2 * nd],     ap, b0);
                mma_f16(oacc[2 * nd + 1], ap, b1);
            }
        }
    }

    // ---- epilogue ----
    float inv0 = 1.0f / ll0, inv1 = 1.0f / ll1;
    int qr = q0 + rql;
    size_t base0 = (((size_t)b << 10) + qr) * DM + (h << 6);
    size_t base1 = base0 + (size_t)8 * DM;
    #pragma unroll
    for (int nd = 0; nd < 8; ++nd) {
        int d = (nd << 3) + cb2;
        *(uint32_t*)(g_chf + base0 + d) = f2h2(oacc[nd][0] * inv0, oacc[nd][1] * inv0);
        *(uint32_t*)(g_chf + base1 + d) = f2h2(oacc[nd][2] * inv1, oacc[nd][3] * inv1);
    }
}

// ---------------------------------------------------------------------------
extern "C" void kernel_launch(void* const* d_in, const int* in_sizes, int n_in,
                              void* d_out, int out_size) {
    (void)in_sizes; (void)n_in; (void)out_size;
    const float* q    = (const float*)d_in[0];
    const float* k    = (const float*)d_in[1];
    const float* v    = (const float*)d_in[2];
    const int*   mask = (const int*)d_in[3];
    const float* Wq = (const float*)d_in[4];
    const float* bq = (const float*)d_in[5];
    const float* Wk = (const float*)d_in[6];
    const float* bk = (const float*)d_in[7];
    const float* Wv = (const float*)d_in[8];
    const float* bv = (const float*)d_in[9];
    const float* Wo = (const float*)d_in[10];
    const float* bo = (const float*)d_in[11];
    float* out = (float*)d_out;

    cudaFuncSetAttribute(gemm_qkv, cudaFuncAttributeMaxDynamicSharedMemorySize, G1_SMEM);
    cudaFuncSetAttribute(gemm_out, cudaFuncAttributeMaxDynamicSharedMemorySize, G2_SMEM);
    cudaFuncSetAttribute(flash_attn, cudaFuncAttributeMaxDynamicSharedMemorySize, F_SMEM);

    dim3 gc((MTOT * DM) / (256 * 4), 3);
    cvt_h<<<gc, 256>>>(q, k, v);
    dim3 tB(32, 8), tG(DM / 32, DM / 32, 4);
    cvt_wT<<<tG, tB>>>(Wq, Wk, Wv, Wo);
    pack_mask_bits<<<(BSZ * SEQL * SEQL / 32) / 8, 256>>>(mask);

    dim3 g1(DM / 128, MTOT / 128, 3);
    gemm_qkv<<<g1, 256, G1_SMEM>>>(bq, bk, bv);

    dim3 gf(SEQL / 128, BSZ * H_);
    flash_attn<<<gf, 256, F_SMEM>>>();

    dim3 g2(DM / 128, MTOT / 128);
    gemm_out<<<g2, 256, G2_SMEM>>>(bo, out);
}

// round 8
// speedup vs baseline: 7.4005x; 1.0848x over previous
#include <cuda_runtime.h>
#include <cuda_fp16.h>
#include <cstdint>

// Problem constants
constexpr int H_   = 16;
constexpr int DM   = 1024;
constexpr int DK   = 64;
constexpr int BSZ  = 8;
constexpr int SEQL = 1024;
constexpr int MTOT = BSZ * SEQL;   // 8192

// ---------------------------------------------------------------------------
// Device scratch
// ---------------------------------------------------------------------------
__device__ __align__(16) __half g_qaf[(size_t)MTOT * DM];
__device__ __align__(16) __half g_kaf[(size_t)MTOT * DM];
__device__ __align__(16) __half g_vaf[(size_t)MTOT * DM];
// transposed weights [N,K] fp16 (hi only for QKV; hi+lo for Wo)
__device__ __align__(16) __half g_wqh[(size_t)DM * DM];
__device__ __align__(16) __half g_wkh[(size_t)DM * DM];
__device__ __align__(16) __half g_wvh[(size_t)DM * DM];
__device__ __align__(16) __half g_woh[(size_t)DM * DM], g_wol[(size_t)DM * DM];
// head-layout projected Q/K/V fp16: [b*H+h][s][d]
__device__ __align__(16) __half g_qhf[(size_t)BSZ * H_ * SEQL * DK];
__device__ __align__(16) __half g_khf[(size_t)BSZ * H_ * SEQL * DK];
__device__ __align__(16) __half g_vhf[(size_t)BSZ * H_ * SEQL * DK];
// concat(ctx) fp16 [8192,1024]
__device__ __align__(16) __half g_chf[(size_t)MTOT * DM];
// bit-packed mask [b][q][k/32]
__device__ __align__(16) uint32_t g_mb[(size_t)BSZ * SEQL * (SEQL / 32)];

// ---------------------------------------------------------------------------
// helpers
// ---------------------------------------------------------------------------
__device__ __forceinline__ uint32_t smem_u32(const void* p) {
    uint32_t a;
    asm("{ .reg .u64 t; cvta.to.shared.u64 t, %1; cvt.u32.u64 %0, t; }"
        : "=r"(a) : "l"(p));
    return a;
}
#define SWZ(o) ((o) ^ (((o) >> 3) & 0x70))

__device__ __forceinline__ void ldsm_x4(uint32_t r[4], uint32_t a) {
    asm volatile("ldmatrix.sync.aligned.m8n8.x4.shared.b16 {%0,%1,%2,%3}, [%4];"
                 : "=r"(r[0]), "=r"(r[1]), "=r"(r[2]), "=r"(r[3]) : "r"(a));
}
__device__ __forceinline__ void ldsm_x4_t(uint32_t r[4], uint32_t a) {
    asm volatile("ldmatrix.sync.aligned.m8n8.x4.trans.shared.b16 {%0,%1,%2,%3}, [%4];"
                 : "=r"(r[0]), "=r"(r[1]), "=r"(r[2]), "=r"(r[3]) : "r"(a));
}
__device__ __forceinline__ void mma_f16(float c[4], const uint32_t a[4], const uint32_t b[2]) {
    asm volatile(
        "mma.sync.aligned.m16n8k16.row.col.f32.f16.f16.f32 "
        "{%0,%1,%2,%3}, {%4,%5,%6,%7}, {%8,%9}, {%0,%1,%2,%3};"
        : "+f"(c[0]), "+f"(c[1]), "+f"(c[2]), "+f"(c[3])
        : "r"(a[0]), "r"(a[1]), "r"(a[2]), "r"(a[3]), "r"(b[0]), "r"(b[1]));
}
#define CP16(s, g) \
    asm volatile("cp.async.cg.shared.global [%0], [%1], 16;" :: "r"(s), "l"(g))
#define CP_COMMIT() asm volatile("cp.async.commit_group;" ::: "memory")
#define CP_WAIT1()  asm volatile("cp.async.wait_group 1;" ::: "memory")

__device__ __forceinline__ uint32_t f2h2(float x, float y) {
    float2 f; f.x = x; f.y = y;
    __half2 h = __float22half2_rn(f);
    return *(uint32_t*)&h;
}

// ---------------------------------------------------------------------------
// Prep kernels
// ---------------------------------------------------------------------------
__global__ __launch_bounds__(256) void cvt_h(const float* __restrict__ q,
                                             const float* __restrict__ k,
                                             const float* __restrict__ v) {
    int z = blockIdx.y;
    const float* X = (z == 0) ? q : (z == 1) ? k : v;
    __half* O = (z == 0) ? g_qaf : (z == 1) ? g_kaf : g_vaf;
    size_t i = ((size_t)blockIdx.x * 256 + threadIdx.x) * 4;
    float4 val = *(const float4*)(X + i);
    *(uint32_t*)(O + i)     = f2h2(val.x, val.y);
    *(uint32_t*)(O + i + 2) = f2h2(val.z, val.w);
}

__global__ __launch_bounds__(256) void cvt_wT(const float* __restrict__ Wq,
                                              const float* __restrict__ Wk,
                                              const float* __restrict__ Wv,
                                              const float* __restrict__ Wo) {
    int z = blockIdx.z;
    const float* W = (z == 0) ? Wq : (z == 1) ? Wk : (z == 2) ? Wv : Wo;
    __half* Hh = (z == 0) ? g_wqh : (z == 1) ? g_wkh : (z == 2) ? g_wvh : g_woh;
    __shared__ float t[32][33];
    int x = blockIdx.x * 32 + threadIdx.x;   // n
    int y = blockIdx.y * 32 + threadIdx.y;   // k
    #pragma unroll
    for (int j = 0; j < 32; j += 8)
        t[threadIdx.y + j][threadIdx.x] = W[(size_t)(y + j) * DM + x];
    __syncthreads();
    int xo = blockIdx.y * 32 + threadIdx.x;  // k
    int yo = blockIdx.x * 32 + threadIdx.y;  // n
    #pragma unroll
    for (int j = 0; j < 32; j += 8) {
        float v = t[threadIdx.x][threadIdx.y + j];
        __half h = __float2half_rn(v);
        Hh[(size_t)(yo + j) * DM + xo] = h;
        if (z == 3)
            g_wol[(size_t)(yo + j) * DM + xo] = __float2half_rn(v - __half2float(h));
    }
}

__global__ __launch_bounds__(256) void pack_mask_bits(const int* __restrict__ m) {
    size_t gw = (size_t)blockIdx.x * 8 + (threadIdx.x >> 5);
    int lane = threadIdx.x & 31;
    int v = m[gw * 32 + lane];
    uint32_t bits = __ballot_sync(0xffffffffu, v != 0);
    if (lane == 0) g_mb[gw] = bits;
}

// ---------------------------------------------------------------------------
// QKV projection: single-term fp16 GEMM, 3-stage ring, grid (8, 64, 3).
// CTA tile 128x128, KC=64, 8 warps (2x4), warp tile 64x32. 2 CTAs/SM.
// ---------------------------------------------------------------------------
constexpr int G1_STGSZ = 32768;              // A 16KB + B 16KB
constexpr int G1_SMEM  = 3 * G1_STGSZ;       // 96KB

extern __shared__ char dsm[];

__device__ __forceinline__ void g1_issue(uint32_t sbase, int stage,
                                         const __half* __restrict__ A,
                                         const __half* __restrict__ B,
                                         int m0, int n0, int kc, int tid)
{
    uint32_t sa = sbase + stage * G1_STGSZ;
    uint32_t sb = sa + 16384;
    #pragma unroll
    for (int i = 0; i < 4; ++i) {
        int idx = tid + (i << 8);
        int row = idx >> 3, c = idx & 7;
        uint32_t so = SWZ(row * 128 + c * 16);
        CP16(sa + so, A + ((size_t)(m0 + row) << 10) + kc + (c << 3));
        CP16(sb + so, B + ((size_t)(n0 + row) << 10) + kc + (c << 3));
    }
}

__global__ __launch_bounds__(256, 2) void gemm_qkv(const float* __restrict__ bq,
                                                   const float* __restrict__ bk,
                                                   const float* __restrict__ bv) {
    const int z = blockIdx.z;
    const __half* A = (z == 0) ? g_qaf : (z == 1) ? g_kaf : g_vaf;
    const __half* B = (z == 0) ? g_wqh : (z == 1) ? g_wkh : g_wvh;
    const float* bias = (z == 0) ? bq : (z == 1) ? bk : bv;
    __half* OF = (z == 0) ? g_qhf : (z == 1) ? g_khf : g_vhf;

    const uint32_t sbase = smem_u32(dsm);
    const int tid = threadIdx.x, lane = tid & 31, wid = tid >> 5;
    const int wm = wid >> 2, wn = wid & 3;
    const int m0 = blockIdx.y << 7, n0 = blockIdx.x << 7;
    const int lrow = lane & 15, lchunk = lane >> 4;

    float acc[4][4][4] = {};

    g1_issue(sbase, 0, A, B, m0, n0, 0, tid);  CP_COMMIT();
    g1_issue(sbase, 1, A, B, m0, n0, 64, tid); CP_COMMIT();

    for (int it = 0; it < 16; ++it) {
        CP_WAIT1();
        __syncthreads();
        int nk = it + 2;
        if (nk < 16) g1_issue(sbase, nk % 3, A, B, m0, n0, nk * 64, tid);
        CP_COMMIT();
        uint32_t sa = sbase + (it % 3) * G1_STGSZ;
        uint32_t sb = sa + 16384;
        #pragma unroll
        for (int c = 0; c < 4; ++c) {
            const int coff = (c << 5) + (lchunk << 4);
            uint32_t aF[4][4];
            #pragma unroll
            for (int f = 0; f < 4; ++f) {
                int r = (wm << 6) + (f << 4) + lrow;
                ldsm_x4(aF[f], sa + SWZ(r * 128 + coff));
            }
            uint32_t bH[4][2];
            #pragma unroll
            for (int p = 0; p < 2; ++p) {
                int r = (wn << 5) + (p << 4) + lrow;
                uint32_t rr[4];
                ldsm_x4(rr, sb + SWZ(r * 128 + coff));
                bH[p * 2][0] = rr[0]; bH[p * 2][1] = rr[2];
                bH[p * 2 + 1][0] = rr[1]; bH[p * 2 + 1][1] = rr[3];
            }
            #pragma unroll
            for (int f = 0; f < 4; ++f)
                #pragma unroll
                for (int n = 0; n < 4; ++n)
                    mma_f16(acc[f][n], aF[f], bH[n]);
        }
    }

    const int lr = lane >> 2, lc = (lane & 3) << 1;
    const float scale = (z == 0) ? 0.125f * 1.44269504f : 1.0f;
    #pragma unroll
    for (int f = 0; f < 4; ++f) {
        #pragma unroll
        for (int half = 0; half < 2; ++half) {
            int m = m0 + (wm << 6) + (f << 4) + lr + (half << 3);
            int b = m >> 10, s = m & 1023;
            #pragma unroll
            for (int n = 0; n < 4; ++n) {
                int ncol = n0 + (wn << 5) + (n << 3) + lc;
                float x0 = acc[f][n][half * 2 + 0] + __ldg(bias + ncol);
                float x1 = acc[f][n][half * 2 + 1] + __ldg(bias + ncol + 1);
                int hh = ncol >> 6, d = ncol & 63;
                size_t off = ((((size_t)b * H_ + hh) << 10) + s) * DK + d;
                *(uint32_t*)(OF + off) = f2h2(x0 * scale, x1 * scale);
            }
        }
    }
}

// ---------------------------------------------------------------------------
// Output projection: 2-term fp16 GEMM (A fp16, B hi/lo), 2-stage, fp32 out.
// 2 CTAs/SM.
// ---------------------------------------------------------------------------
constexpr int G2_STGSZ = 49152;              // A 16KB + Bh 16KB + Bl 16KB
constexpr int G2_SMEM  = 2 * G2_STGSZ;       // 96KB

__device__ __forceinline__ void g2_issue(uint32_t sbase, int stage,
                                         int m0, int n0, int kc, int tid)
{
    uint32_t sa  = sbase + stage * G2_STGSZ;
    uint32_t sbh = sa + 16384;
    uint32_t sbl = sa + 32768;
    #pragma unroll
    for (int i = 0; i < 4; ++i) {
        int idx = tid + (i << 8);
        int row = idx >> 3, c = idx & 7;
        uint32_t so = SWZ(row * 128 + c * 16);
        CP16(sa  + so, g_chf + ((size_t)(m0 + row) << 10) + kc + (c << 3));
        CP16(sbh + so, g_woh + ((size_t)(n0 + row) << 10) + kc + (c << 3));
        CP16(sbl + so, g_wol + ((size_t)(n0 + row) << 10) + kc + (c << 3));
    }
}

__global__ __launch_bounds__(256, 2) void gemm_out(const float* __restrict__ bias,
                                                   float* __restrict__ outF) {
    const uint32_t sbase = smem_u32(dsm);
    const int tid = threadIdx.x, lane = tid & 31, wid = tid >> 5;
    const int wm = wid >> 2, wn = wid & 3;
    const int m0 = blockIdx.y << 7, n0 = blockIdx.x << 7;
    const int lrow = lane & 15, lchunk = lane >> 4;

    float acc[4][4][4] = {};

    g2_issue(sbase, 0, m0, n0, 0, tid);  CP_COMMIT();
    g2_issue(sbase, 1, m0, n0, 64, tid); CP_COMMIT();

    for (int it = 0; it < 16; ++it) {
        CP_WAIT1();
        __syncthreads();
        uint32_t sa  = sbase + (it & 1) * G2_STGSZ;
        uint32_t sbh = sa + 16384;
        uint32_t sbl = sa + 32768;
        #pragma unroll
        for (int c = 0; c < 4; ++c) {
            const int coff = (c << 5) + (lchunk << 4);
            uint32_t aF[4][4];
            #pragma unroll
            for (int f = 0; f < 4; ++f) {
                int r = (wm << 6) + (f << 4) + lrow;
                ldsm_x4(aF[f], sa + SWZ(r * 128 + coff));
            }
            uint32_t bH[4][2], bL[4][2];
            #pragma unroll
            for (int p = 0; p < 2; ++p) {
                int r = (wn << 5) + (p << 4) + lrow;
                uint32_t rr[4];
                ldsm_x4(rr, sbh + SWZ(r * 128 + coff));
                bH[p * 2][0] = rr[0]; bH[p * 2][1] = rr[2];
                bH[p * 2 + 1][0] = rr[1]; bH[p * 2 + 1][1] = rr[3];
                ldsm_x4(rr, sbl + SWZ(r * 128 + coff));
                bL[p * 2][0] = rr[0]; bL[p * 2][1] = rr[2];
                bL[p * 2 + 1][0] = rr[1]; bL[p * 2 + 1][1] = rr[3];
            }
            #pragma unroll
            for (int f = 0; f < 4; ++f)
                #pragma unroll
                for (int n = 0; n < 4; ++n) {
                    mma_f16(acc[f][n], aF[f], bH[n]);
                    mma_f16(acc[f][n], aF[f], bL[n]);
                }
        }
        __syncthreads();
        int nk = it + 2;
        if (nk < 16) g2_issue(sbase, nk & 1, m0, n0, nk * 64, tid);
        CP_COMMIT();
    }

    const int lr = lane >> 2, lc = (lane & 3) << 1;
    #pragma unroll
    for (int f = 0; f < 4; ++f) {
        #pragma unroll
        for (int half = 0; half < 2; ++half) {
            int m = m0 + (wm << 6) + (f << 4) + lr + (half << 3);
            #pragma unroll
            for (int n = 0; n < 4; ++n) {
                int ncol = n0 + (wn << 5) + (n << 3) + lc;
                float2 o;
                o.x = acc[f][n][half * 2 + 0] + __ldg(bias + ncol);
                o.y = acc[f][n][half * 2 + 1] + __ldg(bias + ncol + 1);
                *(float2*)(outF + (size_t)m * DM + ncol) = o;
            }
        }
    }
}

// ---------------------------------------------------------------------------
// Fused flash attention, fp16 HMMA, K-tile 64, 3-stage ring, 2 CTAs/SM.
// ---------------------------------------------------------------------------
constexpr int F_Q   = 0;        // 16 KB
constexpr int F_STG = 16384;
constexpr int F_K = 0, F_V = 8192;
constexpr int F_STGSZ = 16384;                 // K 8KB + V 8KB
constexpr int F_SMEM = F_STG + 3 * F_STGSZ;    // 65536

__device__ __forceinline__ void issue_kv(uint32_t sbase, int stage, int z,
                                         int k0, int tid) {
    uint32_t s = sbase + F_STG + stage * F_STGSZ;
    #pragma unroll
    for (int i = 0; i < 2; ++i) {
        int idx = tid + (i << 8);
        int r = idx >> 3, c = idx & 7;
        uint32_t so = SWZ(r * 128 + c * 16);
        size_t go = ((size_t)z * SEQL + k0 + r) * DK + (c << 3);
        CP16(s + F_K + so, g_khf + go);
        CP16(s + F_V + so, g_vhf + go);
    }
}

__global__ void __launch_bounds__(256, 2) flash_attn() {
    const uint32_t sbase = smem_u32(dsm);
    const int tid = threadIdx.x, lane = tid & 31, w = tid >> 5;
    const int z = blockIdx.y;
    const int b = z >> 4, h = z & 15;
    const int q0 = blockIdx.x << 7;

    // Q tile load
    #pragma unroll
    for (int i = 0; i < 4; ++i) {
        int idx = tid + (i << 8);
        int r = idx >> 3, c = idx & 7;
        uint32_t so = SWZ(r * 128 + c * 16);
        size_t go = ((size_t)z * SEQL + q0 + r) * DK + (c << 3);
        CP16(sbase + F_Q + so, g_qhf + go);
    }
    CP_COMMIT();
    issue_kv(sbase, 0, z, 0, tid);  CP_COMMIT();
    issue_kv(sbase, 1, z, 64, tid); CP_COMMIT();

    CP_WAIT1();
    __syncthreads();

    uint32_t qf[4][4];
    #pragma unroll
    for (int c = 0; c < 4; ++c) {
        int r = (w << 4) + (lane & 15);
        uint32_t coff = (c << 5) + ((lane >> 4) << 4);
        ldsm_x4(qf[c], sbase + F_Q + SWZ(r * 128 + coff));
    }

    float oacc[8][4] = {};
    float ml0 = -1e30f, ml1 = -1e30f, ll0 = 0.f, ll1 = 0.f;
    const int rql = (w << 4) + (lane >> 2);
    const int cb2 = (lane & 3) << 1;
    const uint32_t* mrow0 = g_mb + ((size_t)b * SEQL + q0 + rql) * 32;
    const uint32_t* mrow1 = mrow0 + 8 * 32;

    for (int kt = 0; kt < 16; ++kt) {
        if (kt) { CP_WAIT1(); __syncthreads(); }
        int nk = kt + 2;
        if (nk < 16) issue_kv(sbase, nk % 3, z, nk << 6, tid);
        CP_COMMIT();
        uint32_t s = sbase + F_STG + (kt % 3) * F_STGSZ;

        float sacc[8][4] = {};
        // ---- S = Q K^T (log2 domain via Q scale) ----
        #pragma unroll
        for (int c = 0; c < 4; ++c) {
            #pragma unroll
            for (int p = 0; p < 4; ++p) {
                int r = (p << 4) + (lane & 15);
                uint32_t coff = (c << 5) + ((lane >> 4) << 4);
                uint32_t rh[4];
                ldsm_x4(rh, s + F_K + SWZ(r * 128 + coff));
                uint32_t b0[2] = { rh[0], rh[2] }, b1[2] = { rh[1], rh[3] };
                mma_f16(sacc[2 * p],     qf[c], b0);
                mma_f16(sacc[2 * p + 1], qf[c], b1);
            }
        }

        // ---- mask + online softmax (base-2) ----
        const uint32_t m00 = mrow0[(kt << 1) + 0], m01 = mrow0[(kt << 1) + 1];
        const uint32_t m10 = mrow1[(kt << 1) + 0], m11 = mrow1[(kt << 1) + 1];
        float tm0 = -1e30f, tm1 = -1e30f;
        #pragma unroll
        for (int n = 0; n < 8; ++n) {
            uint32_t w0 = (n < 4) ? m00 : m01;
            uint32_t w1 = (n < 4) ? m10 : m11;
            int bit = ((n & 3) << 3) + cb2;
            float v0 = ((w0 >> bit) & 1u)       ? sacc[n][0] : -1e9f;
            float v1 = ((w0 >> (bit + 1)) & 1u) ? sacc[n][1] : -1e9f;
            float v2 = ((w1 >> bit) & 1u)       ? sacc[n][2] : -1e9f;
            float v3 = ((w1 >> (bit + 1)) & 1u) ? sacc[n][3] : -1e9f;
            sacc[n][0] = v0; sacc[n][1] = v1; sacc[n][2] = v2; sacc[n][3] = v3;
            tm0 = fmaxf(tm0, fmaxf(v0, v1));
            tm1 = fmaxf(tm1, fmaxf(v2, v3));
        }
        tm0 = fmaxf(tm0, __shfl_xor_sync(0xffffffffu, tm0, 1));
        tm0 = fmaxf(tm0, __shfl_xor_sync(0xffffffffu, tm0, 2));
        tm1 = fmaxf(tm1, __shfl_xor_sync(0xffffffffu, tm1, 1));
        tm1 = fmaxf(tm1, __shfl_xor_sync(0xffffffffu, tm1, 2));
        float mn0 = fmaxf(ml0, tm0), mn1 = fmaxf(ml1, tm1);
        float al0 = exp2f(ml0 - mn0), al1 = exp2f(ml1 - mn1);
        ml0 = mn0; ml1 = mn1;
        float ts0 = 0.f, ts1 = 0.f;
        #pragma unroll
        for (int n = 0; n < 8; ++n) {
            float p0 = exp2f(sacc[n][0] - mn0);
            float p1 = exp2f(sacc[n][1] - mn0);
            float p2 = exp2f(sacc[n][2] - mn1);
            float p3 = exp2f(sacc[n][3] - mn1);
            sacc[n][0] = p0; sacc[n][1] = p1; sacc[n][2] = p2; sacc[n][3] = p3;
            ts0 += p0 + p1; ts1 += p2 + p3;
        }
        ts0 += __shfl_xor_sync(0xffffffffu, ts0, 1);
        ts0 += __shfl_xor_sync(0xffffffffu, ts0, 2);
        ts1 += __shfl_xor_sync(0xffffffffu, ts1, 1);
        ts1 += __shfl_xor_sync(0xffffffffu, ts1, 2);
        ll0 = ll0 * al0 + ts0;
        ll1 = ll1 * al1 + ts1;
        #pragma unroll
        for (int nd = 0; nd < 8; ++nd) {
            oacc[nd][0] *= al0; oacc[nd][1] *= al0;
            oacc[nd][2] *= al1; oacc[nd][3] *= al1;
        }

        // ---- O += P V ----
        #pragma unroll
        for (int j = 0; j < 4; ++j) {
            uint32_t ap[4];
            ap[0] = f2h2(sacc[2 * j][0],     sacc[2 * j][1]);
            ap[1] = f2h2(sacc[2 * j][2],     sacc[2 * j][3]);
            ap[2] = f2h2(sacc[2 * j + 1][0], sacc[2 * j + 1][1]);
            ap[3] = f2h2(sacc[2 * j + 1][2], sacc[2 * j + 1][3]);
            #pragma unroll
            for (int nd = 0; nd < 4; ++nd) {
                int r = (j << 4) + (lane & 15);
                uint32_t coff = (nd << 5) + ((lane >> 4) << 4);
                uint32_t vh[4];
                ldsm_x4_t(vh, s + F_V + SWZ(r * 128 + coff));
                uint32_t b0[2] = { vh[0], vh[1] }, b1[2] = { vh[2], vh[3] };
                mma_f16(oacc[2 * nd],     ap, b0);
                mma_f16(oacc[2 * nd + 1], ap, b1);
            }
        }
    }

    // ---- epilogue ----
    float inv0 = 1.0f / ll0, inv1 = 1.0f / ll1;
    int qr = q0 + rql;
    size_t base0 = (((size_t)b << 10) + qr) * DM + (h << 6);
    size_t base1 = base0 + (size_t)8 * DM;
    #pragma unroll
    for (int nd = 0; nd < 8; ++nd) {
        int d = (nd << 3) + cb2;
        *(uint32_t*)(g_chf + base0 + d) = f2h2(oacc[nd][0] * inv0, oacc[nd][1] * inv0);
        *(uint32_t*)(g_chf + base1 + d) = f2h2(oacc[nd][2] * inv1, oacc[nd][3] * inv1);
    }
}

// ---------------------------------------------------------------------------
extern "C" void kernel_launch(void* const* d_in, const int* in_sizes, int n_in,
                              void* d_out, int out_size) {
    (void)in_sizes; (void)n_in; (void)out_size;
    const float* q    = (const float*)d_in[0];
    const float* k    = (const float*)d_in[1];
    const float* v    = (const float*)d_in[2];
    const int*   mask = (const int*)d_in[3];
    const float* Wq = (const float*)d_in[4];
    const float* bq = (const float*)d_in[5];
    const float* Wk = (const float*)d_in[6];
    const float* bk = (const float*)d_in[7];
    const float* Wv = (const float*)d_in[8];
    const float* bv = (const float*)d_in[9];
    const float* Wo = (const float*)d_in[10];
    const float* bo = (const float*)d_in[11];
    float* out = (float*)d_out;

    cudaFuncSetAttribute(gemm_qkv, cudaFuncAttributeMaxDynamicSharedMemorySize, G1_SMEM);
    cudaFuncSetAttribute(gemm_out, cudaFuncAttributeMaxDynamicSharedMemorySize, G2_SMEM);
    cudaFuncSetAttribute(flash_attn, cudaFuncAttributeMaxDynamicSharedMemorySize, F_SMEM);

    dim3 gc((MTOT * DM) / (256 * 4), 3);
    cvt_h<<<gc, 256>>>(q, k, v);
    dim3 tB(32, 8), tG(DM / 32, DM / 32, 4);
    cvt_wT<<<tG, tB>>>(Wq, Wk, Wv, Wo);
    pack_mask_bits<<<(BSZ * SEQL * SEQL / 32) / 8, 256>>>(mask);

    dim3 g1(DM / 128, MTOT / 128, 3);
    gemm_qkv<<<g1, 256, G1_SMEM>>>(bq, bk, bv);

    dim3 gf(SEQL / 128, BSZ * H_);
    flash_attn<<<gf, 256, F_SMEM>>>();

    dim3 g2(DM / 128, MTOT / 128);
    gemm_out<<<g2, 256, G2_SMEM>>>(bo, out);
}

// round 9
// speedup vs baseline: 8.2581x; 1.1159x over previous
#include <cuda_runtime.h>
#include <cuda_fp16.h>
#include <cstdint>

// Problem constants
constexpr int H_   = 16;
constexpr int DM   = 1024;
constexpr int DK   = 64;
constexpr int BSZ  = 8;
constexpr int SEQL = 1024;
constexpr int MTOT = BSZ * SEQL;   // 8192

// ---------------------------------------------------------------------------
// Device scratch
// ---------------------------------------------------------------------------
__device__ __align__(16) __half g_qaf[(size_t)MTOT * DM];
__device__ __align__(16) __half g_kaf[(size_t)MTOT * DM];
__device__ __align__(16) __half g_vaf[(size_t)MTOT * DM];
// transposed weights [N,K] fp16 (hi only)
__device__ __align__(16) __half g_wqh[(size_t)DM * DM];
__device__ __align__(16) __half g_wkh[(size_t)DM * DM];
__device__ __align__(16) __half g_wvh[(size_t)DM * DM];
__device__ __align__(16) __half g_woh[(size_t)DM * DM];
// head-layout projected Q/K/V fp16: [b*H+h][s][d]
__device__ __align__(16) __half g_qhf[(size_t)BSZ * H_ * SEQL * DK];
__device__ __align__(16) __half g_khf[(size_t)BSZ * H_ * SEQL * DK];
__device__ __align__(16) __half g_vhf[(size_t)BSZ * H_ * SEQL * DK];
// concat(ctx) fp16 [8192,1024]
__device__ __align__(16) __half g_chf[(size_t)MTOT * DM];
// bit-packed mask [b][q][k/32]
__device__ __align__(16) uint32_t g_mb[(size_t)BSZ * SEQL * (SEQL / 32)];

// ---------------------------------------------------------------------------
// helpers
// ---------------------------------------------------------------------------
__device__ __forceinline__ uint32_t smem_u32(const void* p) {
    uint32_t a;
    asm("{ .reg .u64 t; cvta.to.shared.u64 t, %1; cvt.u32.u64 %0, t; }"
        : "=r"(a) : "l"(p));
    return a;
}
#define SWZ(o) ((o) ^ (((o) >> 3) & 0x70))

__device__ __forceinline__ void ldsm_x4(uint32_t r[4], uint32_t a) {
    asm volatile("ldmatrix.sync.aligned.m8n8.x4.shared.b16 {%0,%1,%2,%3}, [%4];"
                 : "=r"(r[0]), "=r"(r[1]), "=r"(r[2]), "=r"(r[3]) : "r"(a));
}
__device__ __forceinline__ void ldsm_x4_t(uint32_t r[4], uint32_t a) {
    asm volatile("ldmatrix.sync.aligned.m8n8.x4.trans.shared.b16 {%0,%1,%2,%3}, [%4];"
                 : "=r"(r[0]), "=r"(r[1]), "=r"(r[2]), "=r"(r[3]) : "r"(a));
}
__device__ __forceinline__ void mma_f16(float c[4], const uint32_t a[4], const uint32_t b[2]) {
    asm volatile(
        "mma.sync.aligned.m16n8k16.row.col.f32.f16.f16.f32 "
        "{%0,%1,%2,%3}, {%4,%5,%6,%7}, {%8,%9}, {%0,%1,%2,%3};"
        : "+f"(c[0]), "+f"(c[1]), "+f"(c[2]), "+f"(c[3])
        : "r"(a[0]), "r"(a[1]), "r"(a[2]), "r"(a[3]), "r"(b[0]), "r"(b[1]));
}
#define CP16(s, g) \
    asm volatile("cp.async.cg.shared.global [%0], [%1], 16;" :: "r"(s), "l"(g))
#define CP_COMMIT() asm volatile("cp.async.commit_group;" ::: "memory")
#define CP_WAIT1()  asm volatile("cp.async.wait_group 1;" ::: "memory")

__device__ __forceinline__ uint32_t f2h2(float x, float y) {
    float2 f; f.x = x; f.y = y;
    __half2 h = __float22half2_rn(f);
    return *(uint32_t*)&h;
}

// ---------------------------------------------------------------------------
// Prep kernels
// ---------------------------------------------------------------------------
__global__ __launch_bounds__(256) void cvt_h(const float* __restrict__ q,
                                             const float* __restrict__ k,
                                             const float* __restrict__ v) {
    int z = blockIdx.y;
    const float* X = (z == 0) ? q : (z == 1) ? k : v;
    __half* O = (z == 0) ? g_qaf : (z == 1) ? g_kaf : g_vaf;
    size_t i = ((size_t)blockIdx.x * 256 + threadIdx.x) * 4;
    float4 val = *(const float4*)(X + i);
    *(uint32_t*)(O + i)     = f2h2(val.x, val.y);
    *(uint32_t*)(O + i + 2) = f2h2(val.z, val.w);
}

__global__ __launch_bounds__(256) void cvt_wT(const float* __restrict__ Wq,
                                              const float* __restrict__ Wk,
                                              const float* __restrict__ Wv,
                                              const float* __restrict__ Wo) {
    int z = blockIdx.z;
    const float* W = (z == 0) ? Wq : (z == 1) ? Wk : (z == 2) ? Wv : Wo;
    __half* Hh = (z == 0) ? g_wqh : (z == 1) ? g_wkh : (z == 2) ? g_wvh : g_woh;
    __shared__ float t[32][33];
    int x = blockIdx.x * 32 + threadIdx.x;   // n
    int y = blockIdx.y * 32 + threadIdx.y;   // k
    #pragma unroll
    for (int j = 0; j < 32; j += 8)
        t[threadIdx.y + j][threadIdx.x] = W[(size_t)(y + j) * DM + x];
    __syncthreads();
    int xo = blockIdx.y * 32 + threadIdx.x;  // k
    int yo = blockIdx.x * 32 + threadIdx.y;  // n
    #pragma unroll
    for (int j = 0; j < 32; j += 8)
        Hh[(size_t)(yo + j) * DM + xo] = __float2half_rn(t[threadIdx.x][threadIdx.y + j]);
}

__global__ __launch_bounds__(256) void pack_mask_bits(const int* __restrict__ m) {
    size_t gw = (size_t)blockIdx.x * 8 + (threadIdx.x >> 5);
    int lane = threadIdx.x & 31;
    int v = m[gw * 32 + lane];
    uint32_t bits = __ballot_sync(0xffffffffu, v != 0);
    if (lane == 0) g_mb[gw] = bits;
}

// ---------------------------------------------------------------------------
// Single-term fp16 GEMM core: 3-stage ring, CTA tile 128x128, KC=64,
// 8 warps (2x4), warp tile 64x32, 2 CTAs/SM.
// ---------------------------------------------------------------------------
constexpr int G1_STGSZ = 32768;              // A 16KB + B 16KB
constexpr int G1_SMEM  = 3 * G1_STGSZ;       // 96KB

extern __shared__ char dsm[];

__device__ __forceinline__ void g1_issue(uint32_t sbase, int stage,
                                         const __half* __restrict__ A,
                                         const __half* __restrict__ B,
                                         int m0, int n0, int kc, int tid)
{
    uint32_t sa = sbase + stage * G1_STGSZ;
    uint32_t sb = sa + 16384;
    #pragma unroll
    for (int i = 0; i < 4; ++i) {
        int idx = tid + (i << 8);
        int row = idx >> 3, c = idx & 7;
        uint32_t so = SWZ(row * 128 + c * 16);
        CP16(sa + so, A + ((size_t)(m0 + row) << 10) + kc + (c << 3));
        CP16(sb + so, B + ((size_t)(n0 + row) << 10) + kc + (c << 3));
    }
}

// Shared mainloop producing acc[4][4][4]
__device__ __forceinline__ void g1_mainloop(uint32_t sbase,
                                            const __half* __restrict__ A,
                                            const __half* __restrict__ B,
                                            int m0, int n0, int tid,
                                            float acc[4][4][4]) {
    const int lane = tid & 31, wid = tid >> 5;
    const int wm = wid >> 2, wn = wid & 3;
    const int lrow = lane & 15, lchunk = lane >> 4;

    g1_issue(sbase, 0, A, B, m0, n0, 0, tid);  CP_COMMIT();
    g1_issue(sbase, 1, A, B, m0, n0, 64, tid); CP_COMMIT();

    for (int it = 0; it < 16; ++it) {
        CP_WAIT1();
        __syncthreads();
        int nk = it + 2;
        if (nk < 16) g1_issue(sbase, nk % 3, A, B, m0, n0, nk * 64, tid);
        CP_COMMIT();
        uint32_t sa = sbase + (it % 3) * G1_STGSZ;
        uint32_t sb = sa + 16384;
        #pragma unroll
        for (int c = 0; c < 4; ++c) {
            const int coff = (c << 5) + (lchunk << 4);
            uint32_t aF[4][4];
            #pragma unroll
            for (int f = 0; f < 4; ++f) {
                int r = (wm << 6) + (f << 4) + lrow;
                ldsm_x4(aF[f], sa + SWZ(r * 128 + coff));
            }
            uint32_t bH[4][2];
            #pragma unroll
            for (int p = 0; p < 2; ++p) {
                int r = (wn << 5) + (p << 4) + lrow;
                uint32_t rr[4];
                ldsm_x4(rr, sb + SWZ(r * 128 + coff));
                bH[p * 2][0] = rr[0]; bH[p * 2][1] = rr[2];
                bH[p * 2 + 1][0] = rr[1]; bH[p * 2 + 1][1] = rr[3];
            }
            #pragma unroll
            for (int f = 0; f < 4; ++f)
                #pragma unroll
                for (int n = 0; n < 4; ++n)
                    mma_f16(acc[f][n], aF[f], bH[n]);
        }
    }
}

// QKV projection: grid (8, 64, 3) -> fp16 head layout (Q scaled 0.125*log2e)
__global__ __launch_bounds__(256, 2) void gemm_qkv(const float* __restrict__ bq,
                                                   const float* __restrict__ bk,
                                                   const float* __restrict__ bv) {
    const int z = blockIdx.z;
    const __half* A = (z == 0) ? g_qaf : (z == 1) ? g_kaf : g_vaf;
    const __half* B = (z == 0) ? g_wqh : (z == 1) ? g_wkh : g_wvh;
    const float* bias = (z == 0) ? bq : (z == 1) ? bk : bv;
    __half* OF = (z == 0) ? g_qhf : (z == 1) ? g_khf : g_vhf;

    const uint32_t sbase = smem_u32(dsm);
    const int tid = threadIdx.x, lane = tid & 31, wid = tid >> 5;
    const int wm = wid >> 2, wn = wid & 3;
    const int m0 = blockIdx.y << 7, n0 = blockIdx.x << 7;

    float acc[4][4][4] = {};
    g1_mainloop(sbase, A, B, m0, n0, tid, acc);

    const int lr = lane >> 2, lc = (lane & 3) << 1;
    const float scale = (z == 0) ? 0.125f * 1.44269504f : 1.0f;
    #pragma unroll
    for (int f = 0; f < 4; ++f) {
        #pragma unroll
        for (int half = 0; half < 2; ++half) {
            int m = m0 + (wm << 6) + (f << 4) + lr + (half << 3);
            int b = m >> 10, s = m & 1023;
            #pragma unroll
            for (int n = 0; n < 4; ++n) {
                int ncol = n0 + (wn << 5) + (n << 3) + lc;
                float x0 = acc[f][n][half * 2 + 0] + __ldg(bias + ncol);
                float x1 = acc[f][n][half * 2 + 1] + __ldg(bias + ncol + 1);
                int hh = ncol >> 6, d = ncol & 63;
                size_t off = ((((size_t)b * H_ + hh) << 10) + s) * DK + d;
                *(uint32_t*)(OF + off) = f2h2(x0 * scale, x1 * scale);
            }
        }
    }
}

// Output projection: 1-term, fp32 flat output
__global__ __launch_bounds__(256, 2) void gemm_out(const float* __restrict__ bias,
                                                   float* __restrict__ outF) {
    const uint32_t sbase = smem_u32(dsm);
    const int tid = threadIdx.x, lane = tid & 31, wid = tid >> 5;
    const int wm = wid >> 2, wn = wid & 3;
    const int m0 = blockIdx.y << 7, n0 = blockIdx.x << 7;

    float acc[4][4][4] = {};
    g1_mainloop(sbase, g_chf, g_woh, m0, n0, tid, acc);

    const int lr = lane >> 2, lc = (lane & 3) << 1;
    #pragma unroll
    for (int f = 0; f < 4; ++f) {
        #pragma unroll
        for (int half = 0; half < 2; ++half) {
            int m = m0 + (wm << 6) + (f << 4) + lr + (half << 3);
            #pragma unroll
            for (int n = 0; n < 4; ++n) {
                int ncol = n0 + (wn << 5) + (n << 3) + lc;
                float2 o;
                o.x = acc[f][n][half * 2 + 0] + __ldg(bias + ncol);
                o.y = acc[f][n][half * 2 + 1] + __ldg(bias + ncol + 1);
                *(float2*)(outF + (size_t)m * DM + ncol) = o;
            }
        }
    }
}

// ---------------------------------------------------------------------------
// Fused flash attention, fp16 HMMA, K-tile 64, 3-stage ring, 2 CTAs/SM.
// ---------------------------------------------------------------------------
constexpr int F_Q   = 0;        // 16 KB
constexpr int F_STG = 16384;
constexpr int F_K = 0, F_V = 8192;
constexpr int F_STGSZ = 16384;                 // K 8KB + V 8KB
constexpr int F_SMEM = F_STG + 3 * F_STGSZ;    // 65536

__device__ __forceinline__ void issue_kv(uint32_t sbase, int stage, int z,
                                         int k0, int tid) {
    uint32_t s = sbase + F_STG + stage * F_STGSZ;
    #pragma unroll
    for (int i = 0; i < 2; ++i) {
        int idx = tid + (i << 8);
        int r = idx >> 3, c = idx & 7;
        uint32_t so = SWZ(r * 128 + c * 16);
        size_t go = ((size_t)z * SEQL + k0 + r) * DK + (c << 3);
        CP16(s + F_K + so, g_khf + go);
        CP16(s + F_V + so, g_vhf + go);
    }
}

__global__ void __launch_bounds__(256, 2) flash_attn() {
    const uint32_t sbase = smem_u32(dsm);
    const int tid = threadIdx.x, lane = tid & 31, w = tid >> 5;
    const int z = blockIdx.y;
    const int b = z >> 4, h = z & 15;
    const int q0 = blockIdx.x << 7;

    // Q tile load
    #pragma unroll
    for (int i = 0; i < 4; ++i) {
        int idx = tid + (i << 8);
        int r = idx >> 3, c = idx & 7;
        uint32_t so = SWZ(r * 128 + c * 16);
        size_t go = ((size_t)z * SEQL + q0 + r) * DK + (c << 3);
        CP16(sbase + F_Q + so, g_qhf + go);
    }
    CP_COMMIT();
    issue_kv(sbase, 0, z, 0, tid);  CP_COMMIT();
    issue_kv(sbase, 1, z, 64, tid); CP_COMMIT();

    CP_WAIT1();
    __syncthreads();

    uint32_t qf[4][4];
    #pragma unroll
    for (int c = 0; c < 4; ++c) {
        int r = (w << 4) + (lane & 15);
        uint32_t coff = (c << 5) + ((lane >> 4) << 4);
        ldsm_x4(qf[c], sbase + F_Q + SWZ(r * 128 + coff));
    }

    float oacc[8][4] = {};
    float ml0 = -1e30f, ml1 = -1e30f, ll0 = 0.f, ll1 = 0.f;
    const int rql = (w << 4) + (lane >> 2);
    const int cb2 = (lane & 3) << 1;
    const uint32_t* mrow0 = g_mb + ((size_t)b * SEQL + q0 + rql) * 32;
    const uint32_t* mrow1 = mrow0 + 8 * 32;

    for (int kt = 0; kt < 16; ++kt) {
        if (kt) { CP_WAIT1(); __syncthreads(); }
        int nk = kt + 2;
        if (nk < 16) issue_kv(sbase, nk % 3, z, nk << 6, tid);
        CP_COMMIT();
        uint32_t s = sbase + F_STG + (kt % 3) * F_STGSZ;

        float sacc[8][4] = {};
        // ---- S = Q K^T (log2 domain via Q scale) ----
        #pragma unroll
        for (int c = 0; c < 4; ++c) {
            #pragma unroll
            for (int p = 0; p < 4; ++p) {
                int r = (p << 4) + (lane & 15);
                uint32_t coff = (c << 5) + ((lane >> 4) << 4);
                uint32_t rh[4];
                ldsm_x4(rh, s + F_K + SWZ(r * 128 + coff));
                uint32_t b0[2] = { rh[0], rh[2] }, b1[2] = { rh[1], rh[3] };
                mma_f16(sacc[2 * p],     qf[c], b0);
                mma_f16(sacc[2 * p + 1], qf[c], b1);
            }
        }

        // ---- mask + online softmax (base-2) ----
        const uint32_t m00 = mrow0[(kt << 1) + 0], m01 = mrow0[(kt << 1) + 1];
        const uint32_t m10 = mrow1[(kt << 1) + 0], m11 = mrow1[(kt << 1) + 1];
        float tm0 = -1e30f, tm1 = -1e30f;
        #pragma unroll
        for (int n = 0; n < 8; ++n) {
            uint32_t w0 = (n < 4) ? m00 : m01;
            uint32_t w1 = (n < 4) ? m10 : m11;
            int bit = ((n & 3) << 3) + cb2;
            float v0 = ((w0 >> bit) & 1u)       ? sacc[n][0] : -1e9f;
            float v1 = ((w0 >> (bit + 1)) & 1u) ? sacc[n][1] : -1e9f;
            float v2 = ((w1 >> bit) & 1u)       ? sacc[n][2] : -1e9f;
            float v3 = ((w1 >> (bit + 1)) & 1u) ? sacc[n][3] : -1e9f;
            sacc[n][0] = v0; sacc[n][1] = v1; sacc[n][2] = v2; sacc[n][3] = v3;
            tm0 = fmaxf(tm0, fmaxf(v0, v1));
            tm1 = fmaxf(tm1, fmaxf(v2, v3));
        }
        tm0 = fmaxf(tm0, __shfl_xor_sync(0xffffffffu, tm0, 1));
        tm0 = fmaxf(tm0, __shfl_xor_sync(0xffffffffu, tm0, 2));
        tm1 = fmaxf(tm1, __shfl_xor_sync(0xffffffffu, tm1, 1));
        tm1 = fmaxf(tm1, __shfl_xor_sync(0xffffffffu, tm1, 2));
        float mn0 = fmaxf(ml0, tm0), mn1 = fmaxf(ml1, tm1);
        float al0 = exp2f(ml0 - mn0), al1 = exp2f(ml1 - mn1);
        ml0 = mn0; ml1 = mn1;
        float ts0 = 0.f, ts1 = 0.f;
        #pragma unroll
        for (int n = 0; n < 8; ++n) {
            float p0 = exp2f(sacc[n][0] - mn0);
            float p1 = exp2f(sacc[n][1] - mn0);
            float p2 = exp2f(sacc[n][2] - mn1);
            float p3 = exp2f(sacc[n][3] - mn1);
            sacc[n][0] = p0; sacc[n][1] = p1; sacc[n][2] = p2; sacc[n][3] = p3;
            ts0 += p0 + p1; ts1 += p2 + p3;
        }
        ts0 += __shfl_xor_sync(0xffffffffu, ts0, 1);
        ts0 += __shfl_xor_sync(0xffffffffu, ts0, 2);
        ts1 += __shfl_xor_sync(0xffffffffu, ts1, 1);
        ts1 += __shfl_xor_sync(0xffffffffu, ts1, 2);
        ll0 = ll0 * al0 + ts0;
        ll1 = ll1 * al1 + ts1;
        #pragma unroll
        for (int nd = 0; nd < 8; ++nd) {
            oacc[nd][0] *= al0; oacc[nd][1] *= al0;
            oacc[nd][2] *= al1; oacc[nd][3] *= al1;
        }

        // ---- O += P V ----
        #pragma unroll
        for (int j = 0; j < 4; ++j) {
            uint32_t ap[4];
            ap[0] = f2h2(sacc[2 * j][0],     sacc[2 * j][1]);
            ap[1] = f2h2(sacc[2 * j][2],     sacc[2 * j][3]);
            ap[2] = f2h2(sacc[2 * j + 1][0], sacc[2 * j + 1][1]);
            ap[3] = f2h2(sacc[2 * j + 1][2], sacc[2 * j + 1][3]);
            #pragma unroll
            for (int nd = 0; nd < 4; ++nd) {
                int r = (j << 4) + (lane & 15);
                uint32_t coff = (nd << 5) + ((lane >> 4) << 4);
                uint32_t vh[4];
                ldsm_x4_t(vh, s + F_V + SWZ(r * 128 + coff));
                uint32_t b0[2] = { vh[0], vh[1] }, b1[2] = { vh[2], vh[3] };
                mma_f16(oacc[2 * nd],     ap, b0);
                mma_f16(oacc[2 * nd + 1], ap, b1);
            }
        }
    }

    // ---- epilogue ----
    float inv0 = 1.0f / ll0, inv1 = 1.0f / ll1;
    int qr = q0 + rql;
    size_t base0 = (((size_t)b << 10) + qr) * DM + (h << 6);
    size_t base1 = base0 + (size_t)8 * DM;
    #pragma unroll
    for (int nd = 0; nd < 8; ++nd) {
        int d = (nd << 3) + cb2;
        *(uint32_t*)(g_chf + base0 + d) = f2h2(oacc[nd][0] * inv0, oacc[nd][1] * inv0);
        *(uint32_t*)(g_chf + base1 + d) = f2h2(oacc[nd][2] * inv1, oacc[nd][3] * inv1);
    }
}

// ---------------------------------------------------------------------------
extern "C" void kernel_launch(void* const* d_in, const int* in_sizes, int n_in,
                              void* d_out, int out_size) {
    (void)in_sizes; (void)n_in; (void)out_size;
    const float* q    = (const float*)d_in[0];
    const float* k    = (const float*)d_in[1];
    const float* v    = (const float*)d_in[2];
    const int*   mask = (const int*)d_in[3];
    const float* Wq = (const float*)d_in[4];
    const float* bq = (const float*)d_in[5];
    const float* Wk = (const float*)d_in[6];
    const float* bk = (const float*)d_in[7];
    const float* Wv = (const float*)d_in[8];
    const float* bv = (const float*)d_in[9];
    const float* Wo = (const float*)d_in[10];
    const float* bo = (const float*)d_in[11];
    float* out = (float*)d_out;

    cudaFuncSetAttribute(gemm_qkv, cudaFuncAttributeMaxDynamicSharedMemorySize, G1_SMEM);
    cudaFuncSetAttribute(gemm_out, cudaFuncAttributeMaxDynamicSharedMemorySize, G1_SMEM);
    cudaFuncSetAttribute(flash_attn, cudaFuncAttributeMaxDynamicSharedMemorySize, F_SMEM);

    dim3 gc((MTOT * DM) / (256 * 4), 3);
    cvt_h<<<gc, 256>>>(q, k, v);
    dim3 tB(32, 8), tG(DM / 32, DM / 32, 4);
    cvt_wT<<<tG, tB>>>(Wq, Wk, Wv, Wo);
    pack_mask_bits<<<(BSZ * SEQL * SEQL / 32) / 8, 256>>>(mask);

    dim3 g1(DM / 128, MTOT / 128, 3);
    gemm_qkv<<<g1, 256, G1_SMEM>>>(bq, bk, bv);

    dim3 gf(SEQL / 128, BSZ * H_);
    flash_attn<<<gf, 256, F_SMEM>>>();

    dim3 g2(DM / 128, MTOT / 128);
    gemm_out<<<g2, 256, G1_SMEM>>>(bo, out);
}